// round 1
// baseline (speedup 1.0000x reference)
#include <cuda_runtime.h>
#include <math.h>

#define L  1024
#define D  512
#define NH 8
#define DA 32       // attention dim per head
#define AH 256      // A*H
#define DH 4096     // D*H
#define FF 2048

// -------- scratch (static device globals; no allocation) --------
__device__ float g_xn[L * D];                 // LN0(x)
__device__ float g_qh[NH * L * DA];           // head-major q
__device__ float g_kh[NH * L * DA];           // head-major k
__device__ float g_vh[NH * L * D];            // head-major v
__device__ float g_S[(size_t)NH * L * L];     // masked scores per head
__device__ float g_den[NH * L];               // denominator
__device__ float g_qkvh[NH * L * D];          // S @ V per head
__device__ float g_y[(size_t)L * DH];         // post-LN1 + residual
__device__ float g_h1[L * FF];                // FFN hidden

// -------- block reduce (sum, sumsq) --------
__device__ __forceinline__ float2 block_reduce2(float a, float b) {
    __shared__ float2 sh[16];
    int tid = threadIdx.x;
#pragma unroll
    for (int o = 16; o > 0; o >>= 1) {
        a += __shfl_down_sync(0xffffffffu, a, o);
        b += __shfl_down_sync(0xffffffffu, b, o);
    }
    int wid = tid >> 5, lane = tid & 31;
    int nw = blockDim.x >> 5;
    if (lane == 0) sh[wid] = make_float2(a, b);
    __syncthreads();
    if (wid == 0) {
        float2 v = (lane < nw) ? sh[lane] : make_float2(0.f, 0.f);
        a = v.x; b = v.y;
#pragma unroll
        for (int o = 8; o > 0; o >>= 1) {
            a += __shfl_down_sync(0xffffffffu, a, o);
            b += __shfl_down_sync(0xffffffffu, b, o);
        }
        if (lane == 0) sh[0] = make_float2(a, b);
    }
    __syncthreads();
    return sh[0];
}

// -------- LN over last dim (D=512), 256 threads --------
__global__ void ln0_kernel(const float* __restrict__ x, const float* __restrict__ w,
                           const float* __restrict__ b, float* __restrict__ out) {
    int l = blockIdx.x, tid = threadIdx.x;
    const float* row = x + (size_t)l * D;
    float v0 = row[tid], v1 = row[tid + 256];
    float2 r = block_reduce2(v0 + v1, v0 * v0 + v1 * v1);
    float mu = r.x * (1.0f / D);
    float var = r.y * (1.0f / D) - mu * mu;
    float rs = rsqrtf(var + 1e-5f);
    out[(size_t)l * D + tid]       = (v0 - mu) * rs * w[tid]       + b[tid];
    out[(size_t)l * D + tid + 256] = (v1 - mu) * rs * w[tid + 256] + b[tid + 256];
}

// -------- generic SGEMM: C = A(MxK) @ B(KxN), row-major, with epilogues --------
// EPI: 0 none, 1 exp(clip(v+bias)), 2 v+bias, 3 relu(v+bias), 4 relu(v+bias)+add
// PERM: 0 normal store, 1 head-major store out[((n&7)*M + m)*(N/8) + (n>>3)]
#define BM 128
#define BN 128
#define BK 8

template<int EPI, int PERM>
__global__ void __launch_bounds__(256) sgemm_kernel(
    const float* __restrict__ A, const float* __restrict__ B,
    const float* __restrict__ bias, const float* __restrict__ add,
    float* __restrict__ C, int M, int N, int K)
{
    __shared__ float As[BK][BM];
    __shared__ float Bs[BK][BN];
    int z = blockIdx.z;
    A += (size_t)z * M * K;
    B += (size_t)z * K * N;
    C += (size_t)z * M * N;
    int tid = threadIdx.x;
    int tx = tid & 15, ty = tid >> 4;
    int m0 = blockIdx.y * BM, n0 = blockIdx.x * BN;
    int arow = tid >> 1, acol = (tid & 1) * 4;
    int brow = tid >> 5, bcol = (tid & 31) * 4;
    const float* Ap = A + (size_t)(m0 + arow) * K + acol;
    const float* Bp = B + (size_t)brow * N + n0 + bcol;
    float acc[8][8];
#pragma unroll
    for (int i = 0; i < 8; i++)
#pragma unroll
        for (int j = 0; j < 8; j++) acc[i][j] = 0.f;

    for (int k0 = 0; k0 < K; k0 += BK) {
        float4 av = *(const float4*)Ap;
        float4 bv = *(const float4*)Bp;
        As[acol + 0][arow] = av.x;
        As[acol + 1][arow] = av.y;
        As[acol + 2][arow] = av.z;
        As[acol + 3][arow] = av.w;
        *(float4*)&Bs[brow][bcol] = bv;
        __syncthreads();
#pragma unroll
        for (int k = 0; k < BK; k++) {
            float4 a0 = *(const float4*)&As[k][ty * 8];
            float4 a1 = *(const float4*)&As[k][ty * 8 + 4];
            float4 b0 = *(const float4*)&Bs[k][tx * 8];
            float4 b1 = *(const float4*)&Bs[k][tx * 8 + 4];
            float a[8] = {a0.x, a0.y, a0.z, a0.w, a1.x, a1.y, a1.z, a1.w};
            float bb[8] = {b0.x, b0.y, b0.z, b0.w, b1.x, b1.y, b1.z, b1.w};
#pragma unroll
            for (int i = 0; i < 8; i++)
#pragma unroll
                for (int j = 0; j < 8; j++)
                    acc[i][j] += a[i] * bb[j];
        }
        __syncthreads();
        Ap += BK;
        Bp += (size_t)BK * N;
    }

#pragma unroll
    for (int i = 0; i < 8; i++) {
        int m = m0 + ty * 8 + i;
#pragma unroll
        for (int j = 0; j < 8; j++) {
            int n = n0 + tx * 8 + j;
            float v = acc[i][j];
            if (EPI == 1) v = expf(fminf(fmaxf(v + bias[n], -10.f), 10.f));
            else if (EPI == 2) v = v + bias[n];
            else if (EPI == 3) v = fmaxf(v + bias[n], 0.f);
            else if (EPI == 4) v = fmaxf(v + bias[n], 0.f) + add[(size_t)m * N + n];
            if (PERM == 0) {
                C[(size_t)m * N + n] = v;
            } else {
                int h = n & 7, inner = n >> 3;
                C[((size_t)(h * M + m)) * (N >> 3) + inner] = v;
            }
        }
    }
}

// -------- S_h = tril(Q_h K_h^T), 64x64 tiles, K=32 --------
__global__ void __launch_bounds__(256) qk_kernel(const float* __restrict__ qh,
    const float* __restrict__ kh, float* __restrict__ S)
{
    int h = blockIdx.z;
    const float* Q  = qh + (size_t)h * L * DA;
    const float* Km = kh + (size_t)h * L * DA;
    float* Sh = S + (size_t)h * L * L;
    int m0 = blockIdx.y * 64, n0 = blockIdx.x * 64;
    int tid = threadIdx.x;
    int tx = tid & 15, ty = tid >> 4;
    float acc[4][4];
#pragma unroll
    for (int i = 0; i < 4; i++)
#pragma unroll
        for (int j = 0; j < 4; j++) acc[i][j] = 0.f;

    if (n0 <= m0 + 63) {   // skip compute for fully-masked tiles
        __shared__ float Qs[64][33];
        __shared__ float Ks[64][33];
        for (int i = tid; i < 64 * 32; i += 256) {
            int r = i >> 5, c = i & 31;
            Qs[r][c] = Q[(size_t)(m0 + r) * DA + c];
            Ks[r][c] = Km[(size_t)(n0 + r) * DA + c];
        }
        __syncthreads();
#pragma unroll
        for (int k = 0; k < 32; k++) {
            float a[4], b[4];
#pragma unroll
            for (int i = 0; i < 4; i++) a[i] = Qs[ty * 4 + i][k];
#pragma unroll
            for (int j = 0; j < 4; j++) b[j] = Ks[tx * 4 + j][k];
#pragma unroll
            for (int i = 0; i < 4; i++)
#pragma unroll
                for (int j = 0; j < 4; j++)
                    acc[i][j] += a[i] * b[j];
        }
    }
#pragma unroll
    for (int i = 0; i < 4; i++) {
        int m = m0 + ty * 4 + i;
#pragma unroll
        for (int j = 0; j < 4; j++) {
            int n = n0 + tx * 4 + j;
            Sh[(size_t)m * L + n] = (n <= m) ? acc[i][j] : 0.f;
        }
    }
}

// -------- den[h][l] = rowsum of masked S --------
__global__ void den_kernel(const float* __restrict__ S, float* __restrict__ den) {
    int l = blockIdx.x, h = blockIdx.y, tid = threadIdx.x;
    const float* row = S + ((size_t)h * L + l) * L;
    float s = 0.f;
    for (int i = tid; i <= l; i += 256) s += row[i];
    float2 r = block_reduce2(s, 0.f);
    if (tid == 0) den[h * L + l] = r.x;
}

// -------- y = x[...,None] + LN_{(D,H)}(qkv/den) --------
__global__ void y_kernel(const float* __restrict__ x, const float* __restrict__ qkvh,
                         const float* __restrict__ den, const float* __restrict__ w,
                         const float* __restrict__ b, float* __restrict__ y)
{
    int l = blockIdx.x, tid = threadIdx.x;  // 512 threads
    float t[8];
    float s = 0.f, s2 = 0.f;
#pragma unroll
    for (int r = 0; r < 8; r++) {
        int j = tid + r * 512;
        int h = j & 7, d = j >> 3;
        float v = qkvh[((size_t)(h * L + l)) * D + d] / den[h * L + l];
        t[r] = v; s += v; s2 += v * v;
    }
    float2 red = block_reduce2(s, s2);
    float mu = red.x * (1.0f / DH);
    float rs = rsqrtf(red.y * (1.0f / DH) - mu * mu + 1e-5f);
#pragma unroll
    for (int r = 0; r < 8; r++) {
        int j = tid + r * 512;
        y[(size_t)l * DH + j] = x[(size_t)l * D + (j >> 3)] + (t[r] - mu) * rs * w[j] + b[j];
    }
}

extern "C" void kernel_launch(void* const* d_in, const int* in_sizes, int n_in,
                              void* d_out, int out_size)
{
    const float* x    = (const float*)d_in[0];
    const float* ln0w = (const float*)d_in[1];
    const float* ln0b = (const float*)d_in[2];
    const float* ln1w = (const float*)d_in[3];
    const float* ln1b = (const float*)d_in[4];
    const float* qw   = (const float*)d_in[5];
    const float* qb   = (const float*)d_in[6];
    const float* kw   = (const float*)d_in[7];
    const float* kb   = (const float*)d_in[8];
    const float* vw   = (const float*)d_in[9];
    const float* vb   = (const float*)d_in[10];
    const float* w1   = (const float*)d_in[11];
    const float* b1   = (const float*)d_in[12];
    const float* w2   = (const float*)d_in[13];
    const float* b2   = (const float*)d_in[14];
    float* out = (float*)d_out;

    float *xn, *qh, *kh, *vh, *S, *den, *qkvh, *y, *h1;
    cudaGetSymbolAddress((void**)&xn,   g_xn);
    cudaGetSymbolAddress((void**)&qh,   g_qh);
    cudaGetSymbolAddress((void**)&kh,   g_kh);
    cudaGetSymbolAddress((void**)&vh,   g_vh);
    cudaGetSymbolAddress((void**)&S,    g_S);
    cudaGetSymbolAddress((void**)&den,  g_den);
    cudaGetSymbolAddress((void**)&qkvh, g_qkvh);
    cudaGetSymbolAddress((void**)&y,    g_y);
    cudaGetSymbolAddress((void**)&h1,   g_h1);

    // 1) LN0
    ln0_kernel<<<L, 256>>>(x, ln0w, ln0b, xn);
    // 2) q = exp(clip(xn@qw+qb)), k likewise  -> head-major [8][1024][32]
    sgemm_kernel<1, 1><<<dim3(AH / BN, L / BM), 256>>>(xn, qw, qb, nullptr, qh, L, AH, D);
    sgemm_kernel<1, 1><<<dim3(AH / BN, L / BM), 256>>>(xn, kw, kb, nullptr, kh, L, AH, D);
    // 3) v = x@vw + vb -> head-major [8][1024][512]
    sgemm_kernel<2, 1><<<dim3(DH / BN, L / BM), 256>>>(x, vw, vb, nullptr, vh, L, DH, D);
    // 4) S_h = tril(Q_h K_h^T)
    qk_kernel<<<dim3(16, 16, NH), 256>>>(qh, kh, S);
    // 5) den = rowsum(S)
    den_kernel<<<dim3(L, NH), 256>>>(S, den);
    // 6) qkv_h = S_h @ V_h  (batched over heads)
    sgemm_kernel<0, 0><<<dim3(D / BN, L / BM, NH), 256>>>(S, vh, nullptr, nullptr, qkvh, L, D, L);
    // 7) y = x + LN1(qkv/den)
    y_kernel<<<L, 512>>>(x, qkvh, den, ln1w, ln1b, y);
    // 8) h1 = relu(y@w1 + b1)
    sgemm_kernel<3, 0><<<dim3(FF / BN, L / BM), 256>>>(y, w1, b1, nullptr, h1, L, FF, DH);
    // 9) out = relu(h1@w2 + b2) + x
    sgemm_kernel<4, 0><<<dim3(D / BN, L / BM), 256>>>(h1, w2, b2, x, out, L, D, FF);
}

// round 2
// speedup vs baseline: 2.9745x; 2.9745x over previous
#include <cuda_runtime.h>
#include <math.h>

#define L  1024
#define D  512
#define NH 8
#define DA 32
#define AH 256
#define DH 4096
#define FF 2048

// -------- scratch --------
__device__ float g_xn[L * D];
__device__ float g_qh[NH * L * DA];
__device__ float g_kh[NH * L * DA];
__device__ float g_vh[NH * L * D];
__device__ float g_S[(size_t)NH * L * L];
__device__ float g_den[NH * L];
__device__ float g_qkvh[NH * L * D];
__device__ float g_y[(size_t)L * DH];
__device__ float g_h1[L * FF];

__device__ __forceinline__ float2 block_reduce2(float a, float b) {
    __shared__ float2 sh[16];
    int tid = threadIdx.x;
#pragma unroll
    for (int o = 16; o > 0; o >>= 1) {
        a += __shfl_down_sync(0xffffffffu, a, o);
        b += __shfl_down_sync(0xffffffffu, b, o);
    }
    int wid = tid >> 5, lane = tid & 31;
    int nw = blockDim.x >> 5;
    if (lane == 0) sh[wid] = make_float2(a, b);
    __syncthreads();
    if (wid == 0) {
        float2 v = (lane < nw) ? sh[lane] : make_float2(0.f, 0.f);
        a = v.x; b = v.y;
#pragma unroll
        for (int o = 8; o > 0; o >>= 1) {
            a += __shfl_down_sync(0xffffffffu, a, o);
            b += __shfl_down_sync(0xffffffffu, b, o);
        }
        if (lane == 0) sh[0] = make_float2(a, b);
    }
    __syncthreads();
    return sh[0];
}

__global__ void ln0_kernel(const float* __restrict__ x, const float* __restrict__ w,
                           const float* __restrict__ b, float* __restrict__ out) {
    int l = blockIdx.x, tid = threadIdx.x;
    const float* row = x + (size_t)l * D;
    float v0 = row[tid], v1 = row[tid + 256];
    float2 r = block_reduce2(v0 + v1, v0 * v0 + v1 * v1);
    float mu = r.x * (1.0f / D);
    float var = r.y * (1.0f / D) - mu * mu;
    float rs = rsqrtf(var + 1e-5f);
    out[(size_t)l * D + tid]       = (v0 - mu) * rs * w[tid]       + b[tid];
    out[(size_t)l * D + tid + 256] = (v1 - mu) * rs * w[tid + 256] + b[tid + 256];
}

// ================= tf32 tensor-core GEMM =================
// C(MxN) = A(MxK) @ B(KxN), row-major. Block 128x128, BK=16, 256 threads.
// Warp grid 2x4 -> warp tile 64x32 -> 4x4 mma m16n8k8 tiles.
// EPI: 0 none, 1 exp(clip(+bias)), 2 +bias, 3 relu(+bias), 4 relu(+bias)+add
// PERM: 1 -> head-major store  C[((n&7)*M + m)*(N/8) + (n>>3)]
// CAUSAL: 1 -> A is lower-triangular in (m,k): loop K only to m0+128.

#define TBM 128
#define TBN 128
#define TBK 16

__device__ __forceinline__ unsigned f2tf32(float v) {
    unsigned o;
    asm volatile("cvt.rna.tf32.f32 %0, %1;" : "=r"(o) : "f"(v));
    return o;
}

template<int EPI, int PERM, int CAUSAL>
__global__ void __launch_bounds__(256) tgemm(
    const float* __restrict__ A, const float* __restrict__ B,
    const float* __restrict__ bias, const float* __restrict__ add,
    float* __restrict__ C, int M, int N, int K)
{
    __shared__ float As[2][TBM][TBK + 4];   // [m][k], stride 20 -> conflict-free frag reads
    __shared__ float Bs[2][TBK][TBN + 8];   // [k][n], stride 136 -> conflict-free frag reads

    int z = blockIdx.z;
    A += (size_t)z * M * K;
    B += (size_t)z * K * N;
    C += (size_t)z * M * N;

    int tid = threadIdx.x;
    int wid = tid >> 5, lane = tid & 31;
    int group = lane >> 2, tg = lane & 3;
    int warp_m = wid >> 2, warp_n = wid & 3;   // 2 x 4
    int m0 = blockIdx.y * TBM, n0 = blockIdx.x * TBN;

    int Keff = CAUSAL ? (m0 + TBM < K ? m0 + TBM : K) : K;
    int kTiles = Keff / TBK;

    // global load addressing
    int ar = tid >> 2;            // 0..63 (+64)
    int ac = (tid & 3) * 4;       // 0,4,8,12
    int br = tid >> 5;            // 0..7 (+8)
    int bc = (tid & 31) * 4;      // 0..124
    const float* Ap = A + (size_t)(m0 + ar) * K + ac;
    const float* Bp = B + (size_t)br * N + n0 + bc;

    float c[4][4][4];
#pragma unroll
    for (int i = 0; i < 4; i++)
#pragma unroll
        for (int j = 0; j < 4; j++)
#pragma unroll
            for (int r = 0; r < 4; r++) c[i][j][r] = 0.f;

    // prologue: load tile 0
    float4 av0 = *(const float4*)(Ap);
    float4 av1 = *(const float4*)(Ap + (size_t)64 * K);
    float4 bv0 = *(const float4*)(Bp);
    float4 bv1 = *(const float4*)(Bp + (size_t)8 * N);
    {
        float* a0 = &As[0][ar][ac];
        a0[0] = __uint_as_float(f2tf32(av0.x)); a0[1] = __uint_as_float(f2tf32(av0.y));
        a0[2] = __uint_as_float(f2tf32(av0.z)); a0[3] = __uint_as_float(f2tf32(av0.w));
        float* a1 = &As[0][ar + 64][ac];
        a1[0] = __uint_as_float(f2tf32(av1.x)); a1[1] = __uint_as_float(f2tf32(av1.y));
        a1[2] = __uint_as_float(f2tf32(av1.z)); a1[3] = __uint_as_float(f2tf32(av1.w));
        float* b0 = &Bs[0][br][bc];
        b0[0] = __uint_as_float(f2tf32(bv0.x)); b0[1] = __uint_as_float(f2tf32(bv0.y));
        b0[2] = __uint_as_float(f2tf32(bv0.z)); b0[3] = __uint_as_float(f2tf32(bv0.w));
        float* b1 = &Bs[0][br + 8][bc];
        b1[0] = __uint_as_float(f2tf32(bv1.x)); b1[1] = __uint_as_float(f2tf32(bv1.y));
        b1[2] = __uint_as_float(f2tf32(bv1.z)); b1[3] = __uint_as_float(f2tf32(bv1.w));
    }
    __syncthreads();

    for (int t = 0; t < kTiles; t++) {
        int cur = t & 1;
        if (t + 1 < kTiles) {
            const float* Apn = Ap + (size_t)(t + 1) * TBK;
            const float* Bpn = Bp + (size_t)(t + 1) * TBK * N;
            av0 = *(const float4*)(Apn);
            av1 = *(const float4*)(Apn + (size_t)64 * K);
            bv0 = *(const float4*)(Bpn);
            bv1 = *(const float4*)(Bpn + (size_t)8 * N);
        }
#pragma unroll
        for (int kc = 0; kc < TBK; kc += 8) {
            unsigned a[4][4], b[4][2];
#pragma unroll
            for (int mt = 0; mt < 4; mt++) {
                int r = warp_m * 64 + mt * 16 + group;
                a[mt][0] = __float_as_uint(As[cur][r][kc + tg]);
                a[mt][1] = __float_as_uint(As[cur][r + 8][kc + tg]);
                a[mt][2] = __float_as_uint(As[cur][r][kc + tg + 4]);
                a[mt][3] = __float_as_uint(As[cur][r + 8][kc + tg + 4]);
            }
#pragma unroll
            for (int nt = 0; nt < 4; nt++) {
                int n = warp_n * 32 + nt * 8 + group;
                b[nt][0] = __float_as_uint(Bs[cur][kc + tg][n]);
                b[nt][1] = __float_as_uint(Bs[cur][kc + tg + 4][n]);
            }
#pragma unroll
            for (int mt = 0; mt < 4; mt++)
#pragma unroll
                for (int nt = 0; nt < 4; nt++) {
                    asm volatile(
                        "mma.sync.aligned.m16n8k8.row.col.f32.tf32.tf32.f32 "
                        "{%0,%1,%2,%3}, {%4,%5,%6,%7}, {%8,%9}, {%0,%1,%2,%3};"
                        : "+f"(c[mt][nt][0]), "+f"(c[mt][nt][1]),
                          "+f"(c[mt][nt][2]), "+f"(c[mt][nt][3])
                        : "r"(a[mt][0]), "r"(a[mt][1]), "r"(a[mt][2]), "r"(a[mt][3]),
                          "r"(b[nt][0]), "r"(b[nt][1]));
                }
        }
        if (t + 1 < kTiles) {
            int nxt = cur ^ 1;
            float* a0 = &As[nxt][ar][ac];
            a0[0] = __uint_as_float(f2tf32(av0.x)); a0[1] = __uint_as_float(f2tf32(av0.y));
            a0[2] = __uint_as_float(f2tf32(av0.z)); a0[3] = __uint_as_float(f2tf32(av0.w));
            float* a1 = &As[nxt][ar + 64][ac];
            a1[0] = __uint_as_float(f2tf32(av1.x)); a1[1] = __uint_as_float(f2tf32(av1.y));
            a1[2] = __uint_as_float(f2tf32(av1.z)); a1[3] = __uint_as_float(f2tf32(av1.w));
            float* b0 = &Bs[nxt][br][bc];
            b0[0] = __uint_as_float(f2tf32(bv0.x)); b0[1] = __uint_as_float(f2tf32(bv0.y));
            b0[2] = __uint_as_float(f2tf32(bv0.z)); b0[3] = __uint_as_float(f2tf32(bv0.w));
            float* b1 = &Bs[nxt][br + 8][bc];
            b1[0] = __uint_as_float(f2tf32(bv1.x)); b1[1] = __uint_as_float(f2tf32(bv1.y));
            b1[2] = __uint_as_float(f2tf32(bv1.z)); b1[3] = __uint_as_float(f2tf32(bv1.w));
            __syncthreads();
        }
    }

    // epilogue
#pragma unroll
    for (int mt = 0; mt < 4; mt++) {
#pragma unroll
        for (int nt = 0; nt < 4; nt++) {
#pragma unroll
            for (int r = 0; r < 4; r++) {
                int m = m0 + warp_m * 64 + mt * 16 + group + (r >> 1) * 8;
                int n = n0 + warp_n * 32 + nt * 8 + tg * 2 + (r & 1);
                float v = c[mt][nt][r];
                if (EPI == 1) v = expf(fminf(fmaxf(v + bias[n], -10.f), 10.f));
                else if (EPI == 2) v = v + bias[n];
                else if (EPI == 3) v = fmaxf(v + bias[n], 0.f);
                else if (EPI == 4) v = fmaxf(v + bias[n], 0.f) + add[(size_t)m * N + n];
                if (PERM == 0) {
                    C[(size_t)m * N + n] = v;
                } else {
                    int h = n & 7, inner = n >> 3;
                    C[((size_t)(h * M + m)) * (N >> 3) + inner] = v;
                }
            }
        }
    }
}

// -------- S_h = tril(Q_h K_h^T) (fp32, small) --------
__global__ void __launch_bounds__(256) qk_kernel(const float* __restrict__ qh,
    const float* __restrict__ kh, float* __restrict__ S)
{
    int h = blockIdx.z;
    const float* Q  = qh + (size_t)h * L * DA;
    const float* Km = kh + (size_t)h * L * DA;
    float* Sh = S + (size_t)h * L * L;
    int m0 = blockIdx.y * 64, n0 = blockIdx.x * 64;
    int tid = threadIdx.x;
    int tx = tid & 15, ty = tid >> 4;
    float acc[4][4];
#pragma unroll
    for (int i = 0; i < 4; i++)
#pragma unroll
        for (int j = 0; j < 4; j++) acc[i][j] = 0.f;

    if (n0 <= m0 + 63) {
        __shared__ float Qs[64][33];
        __shared__ float Ks[64][33];
        for (int i = tid; i < 64 * 32; i += 256) {
            int r = i >> 5, c = i & 31;
            Qs[r][c] = Q[(size_t)(m0 + r) * DA + c];
            Ks[r][c] = Km[(size_t)(n0 + r) * DA + c];
        }
        __syncthreads();
#pragma unroll
        for (int k = 0; k < 32; k++) {
            float a[4], b[4];
#pragma unroll
            for (int i = 0; i < 4; i++) a[i] = Qs[ty * 4 + i][k];
#pragma unroll
            for (int j = 0; j < 4; j++) b[j] = Ks[tx * 4 + j][k];
#pragma unroll
            for (int i = 0; i < 4; i++)
#pragma unroll
                for (int j = 0; j < 4; j++)
                    acc[i][j] += a[i] * b[j];
        }
    }
#pragma unroll
    for (int i = 0; i < 4; i++) {
        int m = m0 + ty * 4 + i;
#pragma unroll
        for (int j = 0; j < 4; j++) {
            int n = n0 + tx * 4 + j;
            Sh[(size_t)m * L + n] = (n <= m) ? acc[i][j] : 0.f;
        }
    }
}

__global__ void den_kernel(const float* __restrict__ S, float* __restrict__ den) {
    int l = blockIdx.x, h = blockIdx.y, tid = threadIdx.x;
    const float* row = S + ((size_t)h * L + l) * L;
    float s = 0.f;
    for (int i = tid; i <= l; i += 256) s += row[i];
    float2 r = block_reduce2(s, 0.f);
    if (tid == 0) den[h * L + l] = r.x;
}

__global__ void y_kernel(const float* __restrict__ x, const float* __restrict__ qkvh,
                         const float* __restrict__ den, const float* __restrict__ w,
                         const float* __restrict__ b, float* __restrict__ y)
{
    int l = blockIdx.x, tid = threadIdx.x;  // 512 threads
    float t[8];
    float s = 0.f, s2 = 0.f;
#pragma unroll
    for (int r = 0; r < 8; r++) {
        int j = tid + r * 512;
        int h = j & 7, d = j >> 3;
        float v = qkvh[((size_t)(h * L + l)) * D + d] / den[h * L + l];
        t[r] = v; s += v; s2 += v * v;
    }
    float2 red = block_reduce2(s, s2);
    float mu = red.x * (1.0f / DH);
    float rs = rsqrtf(red.y * (1.0f / DH) - mu * mu + 1e-5f);
#pragma unroll
    for (int r = 0; r < 8; r++) {
        int j = tid + r * 512;
        y[(size_t)l * DH + j] = x[(size_t)l * D + (j >> 3)] + (t[r] - mu) * rs * w[j] + b[j];
    }
}

extern "C" void kernel_launch(void* const* d_in, const int* in_sizes, int n_in,
                              void* d_out, int out_size)
{
    const float* x    = (const float*)d_in[0];
    const float* ln0w = (const float*)d_in[1];
    const float* ln0b = (const float*)d_in[2];
    const float* ln1w = (const float*)d_in[3];
    const float* ln1b = (const float*)d_in[4];
    const float* qw   = (const float*)d_in[5];
    const float* qb   = (const float*)d_in[6];
    const float* kw   = (const float*)d_in[7];
    const float* kb   = (const float*)d_in[8];
    const float* vw   = (const float*)d_in[9];
    const float* vb   = (const float*)d_in[10];
    const float* w1   = (const float*)d_in[11];
    const float* b1   = (const float*)d_in[12];
    const float* w2   = (const float*)d_in[13];
    const float* b2   = (const float*)d_in[14];
    float* out = (float*)d_out;

    float *xn, *qh, *kh, *vh, *S, *den, *qkvh, *y, *h1;
    cudaGetSymbolAddress((void**)&xn,   g_xn);
    cudaGetSymbolAddress((void**)&qh,   g_qh);
    cudaGetSymbolAddress((void**)&kh,   g_kh);
    cudaGetSymbolAddress((void**)&vh,   g_vh);
    cudaGetSymbolAddress((void**)&S,    g_S);
    cudaGetSymbolAddress((void**)&den,  g_den);
    cudaGetSymbolAddress((void**)&qkvh, g_qkvh);
    cudaGetSymbolAddress((void**)&y,    g_y);
    cudaGetSymbolAddress((void**)&h1,   g_h1);

    ln0_kernel<<<L, 256>>>(x, ln0w, ln0b, xn);
    tgemm<1, 1, 0><<<dim3(AH / TBN, L / TBM), 256>>>(xn, qw, qb, nullptr, qh, L, AH, D);
    tgemm<1, 1, 0><<<dim3(AH / TBN, L / TBM), 256>>>(xn, kw, kb, nullptr, kh, L, AH, D);
    tgemm<2, 1, 0><<<dim3(DH / TBN, L / TBM), 256>>>(x, vw, vb, nullptr, vh, L, DH, D);
    qk_kernel<<<dim3(16, 16, NH), 256>>>(qh, kh, S);
    den_kernel<<<dim3(L, NH), 256>>>(S, den);
    tgemm<0, 0, 1><<<dim3(D / TBN, L / TBM, NH), 256>>>(S, vh, nullptr, nullptr, qkvh, L, D, L);
    y_kernel<<<L, 512>>>(x, qkvh, den, ln1w, ln1b, y);
    tgemm<3, 0, 0><<<dim3(FF / TBN, L / TBM), 256>>>(y, w1, b1, nullptr, h1, L, FF, DH);
    tgemm<4, 0, 0><<<dim3(D / TBN, L / TBM), 256>>>(h1, w2, b2, x, out, L, D, FF);
}

// round 3
// speedup vs baseline: 3.9697x; 1.3346x over previous
#include <cuda_runtime.h>
#include <math.h>

#define L  1024
#define D  512
#define NH 8
#define DA 32
#define AH 256
#define DH 4096
#define FF 2048

// -------- scratch --------
__device__ float g_xn[L * D];
__device__ float g_rx[L * D];
__device__ float g_rqw[D * AH];
__device__ float g_rkw[D * AH];
__device__ float g_rvw[D * DH];
__device__ float g_rw1[DH * FF];
__device__ float g_rw2[FF * D];
__device__ float g_qh[NH * L * DA];
__device__ float g_kh[NH * L * DA];
__device__ float g_vh[NH * L * D];
__device__ float g_S[(size_t)NH * L * L];
__device__ float g_den[NH * L];
__device__ float g_qkvh[NH * L * D];
__device__ float g_y[(size_t)L * DH];
__device__ float g_h1[L * FF];
__device__ float g_part[4 * L * D];

__device__ __forceinline__ unsigned f2tf32(float v) {
    unsigned o;
    asm volatile("cvt.rna.tf32.f32 %0, %1;" : "=r"(o) : "f"(v));
    return o;
}
__device__ __forceinline__ float rnd(float v) { return __uint_as_float(f2tf32(v)); }

__device__ __forceinline__ void cpa16(void* s, const void* g) {
    unsigned sa = (unsigned)__cvta_generic_to_shared(s);
    asm volatile("cp.async.cg.shared.global [%0], [%1], 16;\n" :: "r"(sa), "l"(g));
}
#define CP_COMMIT() asm volatile("cp.async.commit_group;\n" ::: "memory")
#define CP_WAIT1()  asm volatile("cp.async.wait_group 1;\n" ::: "memory")

__device__ __forceinline__ float2 block_reduce2(float a, float b) {
    __shared__ float2 sh[16];
    int tid = threadIdx.x;
#pragma unroll
    for (int o = 16; o > 0; o >>= 1) {
        a += __shfl_down_sync(0xffffffffu, a, o);
        b += __shfl_down_sync(0xffffffffu, b, o);
    }
    int wid = tid >> 5, lane = tid & 31;
    int nw = blockDim.x >> 5;
    if (lane == 0) sh[wid] = make_float2(a, b);
    __syncthreads();
    if (wid == 0) {
        float2 v = (lane < nw) ? sh[lane] : make_float2(0.f, 0.f);
        a = v.x; b = v.y;
#pragma unroll
        for (int o = 8; o > 0; o >>= 1) {
            a += __shfl_down_sync(0xffffffffu, a, o);
            b += __shfl_down_sync(0xffffffffu, b, o);
        }
        if (lane == 0) sh[0] = make_float2(a, b);
    }
    __syncthreads();
    return sh[0];
}

// -------- one-shot tf32 rounding of weights + x --------
__global__ void round_multi(const float* __restrict__ qw, const float* __restrict__ kw,
                            const float* __restrict__ vw, const float* __restrict__ w1,
                            const float* __restrict__ w2, const float* __restrict__ x,
                            float* rqw, float* rkw, float* rvw, float* rw1, float* rw2, float* rx)
{
    int q = blockIdx.x * 256 + threadIdx.x;  // quad index, total 3080192
    const float4* s; float4* d; int off;
    if (q < 32768)        { s = (const float4*)qw; d = (float4*)rqw; off = q; }
    else if (q < 65536)   { s = (const float4*)kw; d = (float4*)rkw; off = q - 32768; }
    else if (q < 589824)  { s = (const float4*)vw; d = (float4*)rvw; off = q - 65536; }
    else if (q < 2686976) { s = (const float4*)w1; d = (float4*)rw1; off = q - 589824; }
    else if (q < 2949120) { s = (const float4*)w2; d = (float4*)rw2; off = q - 2686976; }
    else                  { s = (const float4*)x;  d = (float4*)rx;  off = q - 2949120; }
    float4 v = s[off];
    v.x = rnd(v.x); v.y = rnd(v.y); v.z = rnd(v.z); v.w = rnd(v.w);
    d[off] = v;
}

// -------- LN0 (rounded output) --------
__global__ void ln0_kernel(const float* __restrict__ x, const float* __restrict__ w,
                           const float* __restrict__ b, float* __restrict__ out) {
    int l = blockIdx.x, tid = threadIdx.x;
    const float* row = x + (size_t)l * D;
    float v0 = row[tid], v1 = row[tid + 256];
    float2 r = block_reduce2(v0 + v1, v0 * v0 + v1 * v1);
    float mu = r.x * (1.0f / D);
    float var = r.y * (1.0f / D) - mu * mu;
    float rs = rsqrtf(var + 1e-5f);
    out[(size_t)l * D + tid]       = rnd((v0 - mu) * rs * w[tid]       + b[tid]);
    out[(size_t)l * D + tid + 256] = rnd((v1 - mu) * rs * w[tid + 256] + b[tid + 256]);
}

// ================= cp.async tf32 tensor GEMM =================
// Block 128x128, BK=16, 3 stages, 256 threads, warp grid 2x4 (warp 64x32).
// EPI: 0 none, 1 exp(clip(+bias)), 2 +bias, 3 relu(+bias)
// PERM: 1 -> head-major store
// MODE: 0 batched-by-z (A+=z*M*lda,B+=z*K*N,C+=z*M*N), 1 QK2 (z picks set), 2 splitK
#define TBM 128
#define TBN 128
#define TBK 16
#define NSTG 3
#define ASTR 20
#define BSTR 136
#define ASZ (TBM * ASTR)           // 2560 floats / stage
#define BSZ (TBK * BSTR)           // 2176 floats / stage
#define SMEM_BYTES ((NSTG * (ASZ + BSZ)) * 4)

template<int EPI, int PERM, int CAUSAL, int MODE, int ROUND>
__global__ void __launch_bounds__(256, 2) tgemm(
    const float* __restrict__ A, const float* __restrict__ B,
    const float* __restrict__ bias, float* __restrict__ C,
    const float* __restrict__ B2, const float* __restrict__ bias2, float* __restrict__ C2,
    int M, int N, int K, int lda)
{
    extern __shared__ float smem[];
    float* Asm = smem;
    float* Bsm = smem + NSTG * ASZ;

    int z = blockIdx.z;
    if (MODE == 0) {
        A += (size_t)z * M * lda;
        B += (size_t)z * K * N;
        C += (size_t)z * M * N;
    } else if (MODE == 1) {
        if (z == 1) { B = B2; bias = bias2; C = C2; }
    } else { // splitK
        A += (size_t)z * K;
        B += (size_t)z * K * N;
        C += (size_t)z * M * N;
    }

    int tid = threadIdx.x;
    int wid = tid >> 5, lane = tid & 31;
    int group = lane >> 2, tg = lane & 3;
    int warp_m = wid >> 2, warp_n = wid & 3;
    int m0 = blockIdx.y * TBM, n0 = blockIdx.x * TBN;

    int Keff = CAUSAL ? (m0 + TBM < K ? m0 + TBM : K) : K;
    int kTiles = Keff / TBK;

    int ar = tid >> 1, ac8 = (tid & 1) * 8;
    int br = tid >> 5, bc = (tid & 31) * 4;
    const float* Abase = A + (size_t)(m0 + ar) * lda + ac8;
    const float* Bbase = B + (size_t)br * N + n0 + bc;

    float c[4][4][4];
#pragma unroll
    for (int i = 0; i < 4; i++)
#pragma unroll
        for (int j = 0; j < 4; j++)
#pragma unroll
            for (int r = 0; r < 4; r++) c[i][j][r] = 0.f;

    // prologue: stages 0..NSTG-2
#pragma unroll
    for (int s = 0; s < NSTG - 1; s++) {
        if (s < kTiles) {
            float* as = Asm + s * ASZ;
            float* bs = Bsm + s * BSZ;
            const float* Ap = Abase + s * TBK;
            const float* Bp = Bbase + (size_t)s * TBK * N;
            cpa16(as + ar * ASTR + ac8,     Ap);
            cpa16(as + ar * ASTR + ac8 + 4, Ap + 4);
            cpa16(bs + br * BSTR + bc,       Bp);
            cpa16(bs + (br + 8) * BSTR + bc, Bp + (size_t)8 * N);
        }
        CP_COMMIT();
    }
    CP_WAIT1();
    __syncthreads();

    int cur = 0;
    for (int t = 0; t < kTiles; t++) {
        // issue prefetch for t+NSTG-1
        int tp = t + NSTG - 1;
        if (tp < kTiles) {
            int ps = tp % NSTG;
            float* as = Asm + ps * ASZ;
            float* bs = Bsm + ps * BSZ;
            const float* Ap = Abase + tp * TBK;
            const float* Bp = Bbase + (size_t)tp * TBK * N;
            cpa16(as + ar * ASTR + ac8,     Ap);
            cpa16(as + ar * ASTR + ac8 + 4, Ap + 4);
            cpa16(bs + br * BSTR + bc,       Bp);
            cpa16(bs + (br + 8) * BSTR + bc, Bp + (size_t)8 * N);
        }
        CP_COMMIT();

        float* as = Asm + cur * ASZ;
        float* bs = Bsm + cur * BSZ;
#pragma unroll
        for (int kc = 0; kc < TBK; kc += 8) {
            unsigned a[4][4], b[4][2];
#pragma unroll
            for (int mt = 0; mt < 4; mt++) {
                int r = warp_m * 64 + mt * 16 + group;
                a[mt][0] = __float_as_uint(as[r * ASTR + kc + tg]);
                a[mt][1] = __float_as_uint(as[(r + 8) * ASTR + kc + tg]);
                a[mt][2] = __float_as_uint(as[r * ASTR + kc + tg + 4]);
                a[mt][3] = __float_as_uint(as[(r + 8) * ASTR + kc + tg + 4]);
            }
#pragma unroll
            for (int nt = 0; nt < 4; nt++) {
                int n = warp_n * 32 + nt * 8 + group;
                b[nt][0] = __float_as_uint(bs[(kc + tg) * BSTR + n]);
                b[nt][1] = __float_as_uint(bs[(kc + tg + 4) * BSTR + n]);
            }
#pragma unroll
            for (int mt = 0; mt < 4; mt++)
#pragma unroll
                for (int nt = 0; nt < 4; nt++) {
                    asm volatile(
                        "mma.sync.aligned.m16n8k8.row.col.f32.tf32.tf32.f32 "
                        "{%0,%1,%2,%3}, {%4,%5,%6,%7}, {%8,%9}, {%0,%1,%2,%3};"
                        : "+f"(c[mt][nt][0]), "+f"(c[mt][nt][1]),
                          "+f"(c[mt][nt][2]), "+f"(c[mt][nt][3])
                        : "r"(a[mt][0]), "r"(a[mt][1]), "r"(a[mt][2]), "r"(a[mt][3]),
                          "r"(b[nt][0]), "r"(b[nt][1]));
                }
        }
        CP_WAIT1();
        __syncthreads();
        cur = (cur == NSTG - 1) ? 0 : cur + 1;
    }

#pragma unroll
    for (int mt = 0; mt < 4; mt++) {
#pragma unroll
        for (int nt = 0; nt < 4; nt++) {
#pragma unroll
            for (int r = 0; r < 4; r++) {
                int m = m0 + warp_m * 64 + mt * 16 + group + (r >> 1) * 8;
                int n = n0 + warp_n * 32 + nt * 8 + tg * 2 + (r & 1);
                float v = c[mt][nt][r];
                if (EPI == 1) v = expf(fminf(fmaxf(v + bias[n], -10.f), 10.f));
                else if (EPI == 2) v = v + bias[n];
                else if (EPI == 3) v = fmaxf(v + bias[n], 0.f);
                if (ROUND) v = rnd(v);
                if (PERM == 0) {
                    C[(size_t)m * N + n] = v;
                } else {
                    int h = n & 7, inner = n >> 3;
                    C[((size_t)(h * M + m)) * (N >> 3) + inner] = v;
                }
            }
        }
    }
}

// -------- S_h = tril(Q_h K_h^T) on tensor cores, 64x64 tiles --------
__global__ void __launch_bounds__(128) qks_kernel(const float* __restrict__ qh,
    const float* __restrict__ kh, float* __restrict__ S)
{
    int h = blockIdx.z;
    int m0 = blockIdx.y * 64, n0 = blockIdx.x * 64;
    float* Sh = S + (size_t)h * L * L;
    int tid = threadIdx.x;

    if (n0 > m0 + 63) {  // fully masked: zero-fill
        float4 zz = make_float4(0.f, 0.f, 0.f, 0.f);
        for (int i = tid; i < 1024; i += 128) {
            int r = i >> 4, cc = (i & 15) * 4;
            *(float4*)&Sh[(size_t)(m0 + r) * L + n0 + cc] = zz;
        }
        return;
    }

    __shared__ float Qs[64][36];
    __shared__ float Ks[64][36];
    const float* Q  = qh + ((size_t)h * L + m0) * DA;
    const float* Kk = kh + ((size_t)h * L + n0) * DA;
    for (int i = tid; i < 512; i += 128) {
        int r = i >> 3, cc = (i & 7) * 4;
        *(float4*)&Qs[r][cc] = *(const float4*)&Q[r * DA + cc];
        *(float4*)&Ks[r][cc] = *(const float4*)&Kk[r * DA + cc];
    }
    __syncthreads();

    int wid = tid >> 5, lane = tid & 31;
    int group = lane >> 2, tg = lane & 3;
    int warp_m = wid >> 1, warp_n = wid & 1;

    float c[2][4][4];
#pragma unroll
    for (int i = 0; i < 2; i++)
#pragma unroll
        for (int j = 0; j < 4; j++)
#pragma unroll
            for (int r = 0; r < 4; r++) c[i][j][r] = 0.f;

#pragma unroll
    for (int kc = 0; kc < 32; kc += 8) {
        unsigned a[2][4], b[4][2];
#pragma unroll
        for (int mt = 0; mt < 2; mt++) {
            int r = warp_m * 32 + mt * 16 + group;
            a[mt][0] = __float_as_uint(Qs[r][kc + tg]);
            a[mt][1] = __float_as_uint(Qs[r + 8][kc + tg]);
            a[mt][2] = __float_as_uint(Qs[r][kc + tg + 4]);
            a[mt][3] = __float_as_uint(Qs[r + 8][kc + tg + 4]);
        }
#pragma unroll
        for (int nt = 0; nt < 4; nt++) {
            int n = warp_n * 32 + nt * 8 + group;
            b[nt][0] = __float_as_uint(Ks[n][kc + tg]);
            b[nt][1] = __float_as_uint(Ks[n][kc + tg + 4]);
        }
#pragma unroll
        for (int mt = 0; mt < 2; mt++)
#pragma unroll
            for (int nt = 0; nt < 4; nt++) {
                asm volatile(
                    "mma.sync.aligned.m16n8k8.row.col.f32.tf32.tf32.f32 "
                    "{%0,%1,%2,%3}, {%4,%5,%6,%7}, {%8,%9}, {%0,%1,%2,%3};"
                    : "+f"(c[mt][nt][0]), "+f"(c[mt][nt][1]),
                      "+f"(c[mt][nt][2]), "+f"(c[mt][nt][3])
                    : "r"(a[mt][0]), "r"(a[mt][1]), "r"(a[mt][2]), "r"(a[mt][3]),
                      "r"(b[nt][0]), "r"(b[nt][1]));
            }
    }

#pragma unroll
    for (int mt = 0; mt < 2; mt++)
#pragma unroll
        for (int nt = 0; nt < 4; nt++)
#pragma unroll
            for (int r = 0; r < 4; r++) {
                int m = m0 + warp_m * 32 + mt * 16 + group + (r >> 1) * 8;
                int n = n0 + warp_n * 32 + nt * 8 + tg * 2 + (r & 1);
                Sh[(size_t)m * L + n] = (n <= m) ? rnd(c[mt][nt][r]) : 0.f;
            }
}

__global__ void den_kernel(const float* __restrict__ S, float* __restrict__ den) {
    int l = blockIdx.x, h = blockIdx.y, tid = threadIdx.x;
    const float* row = S + ((size_t)h * L + l) * L;
    float s = 0.f;
    for (int i = tid; i <= l; i += 256) s += row[i];
    float2 r = block_reduce2(s, 0.f);
    if (tid == 0) den[h * L + l] = r.x;
}

__global__ void y_kernel(const float* __restrict__ x, const float* __restrict__ qkvh,
                         const float* __restrict__ den, const float* __restrict__ w,
                         const float* __restrict__ b, float* __restrict__ y)
{
    int l = blockIdx.x, tid = threadIdx.x;  // 512 threads
    float t[8];
    float s = 0.f, s2 = 0.f;
#pragma unroll
    for (int r = 0; r < 8; r++) {
        int j = tid + r * 512;
        int h = j & 7, d = j >> 3;
        float v = qkvh[((size_t)(h * L + l)) * D + d] / den[h * L + l];
        t[r] = v; s += v; s2 += v * v;
    }
    float2 red = block_reduce2(s, s2);
    float mu = red.x * (1.0f / DH);
    float rs = rsqrtf(red.y * (1.0f / DH) - mu * mu + 1e-5f);
#pragma unroll
    for (int r = 0; r < 8; r++) {
        int j = tid + r * 512;
        y[(size_t)l * DH + j] = rnd(x[(size_t)l * D + (j >> 3)] + (t[r] - mu) * rs * w[j] + b[j]);
    }
}

// -------- split-K reduce + relu + bias + residual --------
__global__ void reduce_out(const float* __restrict__ part, const float* __restrict__ b2,
                           const float* __restrict__ x, float* __restrict__ out)
{
    int q = blockIdx.x * 256 + threadIdx.x;   // quad over 1024*512
    const float4* p = (const float4*)part;
    float4 v0 = p[q];
    float4 v1 = p[q + 131072];
    float4 v2 = p[q + 262144];
    float4 v3 = p[q + 393216];
    float4 bb = ((const float4*)b2)[q & 127];
    float4 xx = ((const float4*)x)[q];
    float4 o;
    o.x = fmaxf(v0.x + v1.x + v2.x + v3.x + bb.x, 0.f) + xx.x;
    o.y = fmaxf(v0.y + v1.y + v2.y + v3.y + bb.y, 0.f) + xx.y;
    o.z = fmaxf(v0.z + v1.z + v2.z + v3.z + bb.z, 0.f) + xx.z;
    o.w = fmaxf(v0.w + v1.w + v2.w + v3.w + bb.w, 0.f) + xx.w;
    ((float4*)out)[q] = o;
}

extern "C" void kernel_launch(void* const* d_in, const int* in_sizes, int n_in,
                              void* d_out, int out_size)
{
    const float* x    = (const float*)d_in[0];
    const float* ln0w = (const float*)d_in[1];
    const float* ln0b = (const float*)d_in[2];
    const float* ln1w = (const float*)d_in[3];
    const float* ln1b = (const float*)d_in[4];
    const float* qw   = (const float*)d_in[5];
    const float* qb   = (const float*)d_in[6];
    const float* kw   = (const float*)d_in[7];
    const float* kb   = (const float*)d_in[8];
    const float* vw   = (const float*)d_in[9];
    const float* vb   = (const float*)d_in[10];
    const float* w1   = (const float*)d_in[11];
    const float* b1   = (const float*)d_in[12];
    const float* w2   = (const float*)d_in[13];
    const float* b2   = (const float*)d_in[14];
    float* out = (float*)d_out;

    float *xn, *rx, *rqw, *rkw, *rvw, *rw1, *rw2;
    float *qh, *kh, *vh, *S, *den, *qkvh, *y, *h1, *part;
    cudaGetSymbolAddress((void**)&xn,   g_xn);
    cudaGetSymbolAddress((void**)&rx,   g_rx);
    cudaGetSymbolAddress((void**)&rqw,  g_rqw);
    cudaGetSymbolAddress((void**)&rkw,  g_rkw);
    cudaGetSymbolAddress((void**)&rvw,  g_rvw);
    cudaGetSymbolAddress((void**)&rw1,  g_rw1);
    cudaGetSymbolAddress((void**)&rw2,  g_rw2);
    cudaGetSymbolAddress((void**)&qh,   g_qh);
    cudaGetSymbolAddress((void**)&kh,   g_kh);
    cudaGetSymbolAddress((void**)&vh,   g_vh);
    cudaGetSymbolAddress((void**)&S,    g_S);
    cudaGetSymbolAddress((void**)&den,  g_den);
    cudaGetSymbolAddress((void**)&qkvh, g_qkvh);
    cudaGetSymbolAddress((void**)&y,    g_y);
    cudaGetSymbolAddress((void**)&h1,   g_h1);
    cudaGetSymbolAddress((void**)&part, g_part);

    // opt into >48KB dynamic smem (idempotent, host-side)
    cudaFuncSetAttribute(tgemm<1,1,0,1,1>, cudaFuncAttributeMaxDynamicSharedMemorySize, SMEM_BYTES);
    cudaFuncSetAttribute(tgemm<2,1,0,0,1>, cudaFuncAttributeMaxDynamicSharedMemorySize, SMEM_BYTES);
    cudaFuncSetAttribute(tgemm<0,0,1,0,0>, cudaFuncAttributeMaxDynamicSharedMemorySize, SMEM_BYTES);
    cudaFuncSetAttribute(tgemm<3,0,0,0,1>, cudaFuncAttributeMaxDynamicSharedMemorySize, SMEM_BYTES);
    cudaFuncSetAttribute(tgemm<0,0,0,2,0>, cudaFuncAttributeMaxDynamicSharedMemorySize, SMEM_BYTES);

    // 0) round weights + x to tf32
    round_multi<<<12032, 256>>>(qw, kw, vw, w1, w2, x, rqw, rkw, rvw, rw1, rw2, rx);
    // 1) LN0 (rounded)
    ln0_kernel<<<L, 256>>>(x, ln0w, ln0b, xn);
    // 2) q,k projections (merged, exp-clip, head-major, rounded)
    tgemm<1,1,0,1,1><<<dim3(AH/TBN, L/TBM, 2), 256, SMEM_BYTES>>>(
        xn, rqw, qb, qh, rkw, kb, kh, L, AH, D, D);
    // 3) v projection (+bias, head-major, rounded)
    tgemm<2,1,0,0,1><<<dim3(DH/TBN, L/TBM), 256, SMEM_BYTES>>>(
        rx, rvw, vb, vh, nullptr, nullptr, nullptr, L, DH, D, D);
    // 4) S = tril(QK^T) per head (tensor, rounded)
    qks_kernel<<<dim3(16, 16, NH), 128>>>(qh, kh, S);
    // 5) den = rowsum(S)
    den_kernel<<<dim3(L, NH), 256>>>(S, den);
    // 6) qkv = S @ V (batched, causal K-trim)
    tgemm<0,0,1,0,0><<<dim3(D/TBN, L/TBM, NH), 256, SMEM_BYTES>>>(
        S, vh, nullptr, qkvh, nullptr, nullptr, nullptr, L, D, L, L);
    // 7) y = x + LN1(qkv/den) (rounded)
    y_kernel<<<L, 512>>>(x, qkvh, den, ln1w, ln1b, y);
    // 8) h1 = relu(y@w1+b1) (rounded)
    tgemm<3,0,0,0,1><<<dim3(FF/TBN, L/TBM), 256, SMEM_BYTES>>>(
        y, rw1, b1, h1, nullptr, nullptr, nullptr, L, FF, DH, DH);
    // 9) split-K=4 partials of h1@w2
    tgemm<0,0,0,2,0><<<dim3(D/TBN, L/TBM, 4), 256, SMEM_BYTES>>>(
        h1, rw2, nullptr, part, nullptr, nullptr, nullptr, L, D, FF/4, FF);
    // 10) out = relu(sum+b2)+x
    reduce_out<<<512, 256>>>(part, b2, x, out);
}

// round 4
// speedup vs baseline: 4.1900x; 1.0555x over previous
#include <cuda_runtime.h>
#include <math.h>

#define L  1024
#define D  512
#define NH 8
#define DA 32
#define AH 256
#define DH 4096
#define FF 2048

// -------- scratch --------
__device__ float g_xn[L * D];
__device__ float g_rx[L * D];
__device__ float g_rqw[D * AH];
__device__ float g_rkw[D * AH];
__device__ float g_rvw[D * DH];
__device__ float g_rw1[DH * FF];
__device__ float g_rw2[FF * D];
__device__ float g_qh[NH * L * DA];
__device__ float g_kh[NH * L * DA];
__device__ float g_vh[NH * L * D];
__device__ float g_S[(size_t)NH * L * L];
__device__ float g_den[NH * L];
__device__ float g_qkvh[NH * L * D];
__device__ float g_y[(size_t)L * DH];
__device__ float g_h1[L * FF];
__device__ float g_part[4 * L * D];
__device__ float g_parth[2 * L * FF];

__device__ __forceinline__ unsigned f2tf32(float v) {
    unsigned o;
    asm volatile("cvt.rna.tf32.f32 %0, %1;" : "=r"(o) : "f"(v));
    return o;
}
__device__ __forceinline__ float rnd(float v) { return __uint_as_float(f2tf32(v)); }

__device__ __forceinline__ void cpa16(void* s, const void* g) {
    unsigned sa = (unsigned)__cvta_generic_to_shared(s);
    asm volatile("cp.async.cg.shared.global [%0], [%1], 16;\n" :: "r"(sa), "l"(g));
}
#define CP_COMMIT() asm volatile("cp.async.commit_group;\n" ::: "memory")
#define CP_WAIT2()  asm volatile("cp.async.wait_group 2;\n" ::: "memory")

__device__ __forceinline__ void ldsm4(unsigned& r0, unsigned& r1, unsigned& r2, unsigned& r3,
                                      unsigned addr) {
    asm volatile("ldmatrix.sync.aligned.m8n8.x4.shared.b16 {%0,%1,%2,%3}, [%4];"
                 : "=r"(r0), "=r"(r1), "=r"(r2), "=r"(r3) : "r"(addr));
}

__device__ __forceinline__ float2 block_reduce2(float a, float b) {
    __shared__ float2 sh[16];
    int tid = threadIdx.x;
#pragma unroll
    for (int o = 16; o > 0; o >>= 1) {
        a += __shfl_down_sync(0xffffffffu, a, o);
        b += __shfl_down_sync(0xffffffffu, b, o);
    }
    int wid = tid >> 5, lane = tid & 31;
    int nw = blockDim.x >> 5;
    if (lane == 0) sh[wid] = make_float2(a, b);
    __syncthreads();
    if (wid == 0) {
        float2 v = (lane < nw) ? sh[lane] : make_float2(0.f, 0.f);
        a = v.x; b = v.y;
#pragma unroll
        for (int o = 8; o > 0; o >>= 1) {
            a += __shfl_down_sync(0xffffffffu, a, o);
            b += __shfl_down_sync(0xffffffffu, b, o);
        }
        if (lane == 0) sh[0] = make_float2(a, b);
    }
    __syncthreads();
    return sh[0];
}

// -------- one-shot tf32 rounding of weights + x --------
__global__ void round_multi(const float* __restrict__ qw, const float* __restrict__ kw,
                            const float* __restrict__ vw, const float* __restrict__ w1,
                            const float* __restrict__ w2, const float* __restrict__ x,
                            float* rqw, float* rkw, float* rvw, float* rw1, float* rw2, float* rx)
{
    int q = blockIdx.x * 256 + threadIdx.x;
    const float4* s; float4* d; int off;
    if (q < 32768)        { s = (const float4*)qw; d = (float4*)rqw; off = q; }
    else if (q < 65536)   { s = (const float4*)kw; d = (float4*)rkw; off = q - 32768; }
    else if (q < 589824)  { s = (const float4*)vw; d = (float4*)rvw; off = q - 65536; }
    else if (q < 2686976) { s = (const float4*)w1; d = (float4*)rw1; off = q - 589824; }
    else if (q < 2949120) { s = (const float4*)w2; d = (float4*)rw2; off = q - 2686976; }
    else                  { s = (const float4*)x;  d = (float4*)rx;  off = q - 2949120; }
    float4 v = s[off];
    v.x = rnd(v.x); v.y = rnd(v.y); v.z = rnd(v.z); v.w = rnd(v.w);
    d[off] = v;
}

__global__ void ln0_kernel(const float* __restrict__ x, const float* __restrict__ w,
                           const float* __restrict__ b, float* __restrict__ out) {
    int l = blockIdx.x, tid = threadIdx.x;
    const float* row = x + (size_t)l * D;
    float v0 = row[tid], v1 = row[tid + 256];
    float2 r = block_reduce2(v0 + v1, v0 * v0 + v1 * v1);
    float mu = r.x * (1.0f / D);
    float var = r.y * (1.0f / D) - mu * mu;
    float rs = rsqrtf(var + 1e-5f);
    out[(size_t)l * D + tid]       = rnd((v0 - mu) * rs * w[tid]       + b[tid]);
    out[(size_t)l * D + tid + 256] = rnd((v1 - mu) * rs * w[tid + 256] + b[tid + 256]);
}

// ================= cp.async tf32 tensor GEMM (ldmatrix A-frags) =================
#define TBM 128
#define TBN 128
#define TBK 16
#define NSTG 4
#define ASTR 20
#define BSTR 136
#define ASZ (TBM * ASTR)
#define BSZ (TBK * BSTR)
#define SMEM_BYTES ((NSTG * (ASZ + BSZ)) * 4)

// EPI: 0 none, 1 exp(clip(+bias)), 2 +bias, 3 relu(+bias)
// MODE: 0 batched-by-z, 1 QK two-sets, 2 splitK
template<int EPI, int PERM, int CAUSAL, int MODE, int ROUND>
__global__ void __launch_bounds__(256, 2) tgemm(
    const float* __restrict__ A, const float* __restrict__ B,
    const float* __restrict__ bias, float* __restrict__ C,
    const float* __restrict__ B2, const float* __restrict__ bias2, float* __restrict__ C2,
    int M, int N, int K, int lda)
{
    extern __shared__ float smem[];
    float* Asm = smem;
    float* Bsm = smem + NSTG * ASZ;

    int z = blockIdx.z;
    if (MODE == 0) {
        A += (size_t)z * M * lda;
        B += (size_t)z * K * N;
        C += (size_t)z * M * N;
    } else if (MODE == 1) {
        if (z == 1) { B = B2; bias = bias2; C = C2; }
    } else {
        A += (size_t)z * K;
        B += (size_t)z * K * N;
        C += (size_t)z * M * N;
    }

    int tid = threadIdx.x;
    int wid = tid >> 5, lane = tid & 31;
    int group = lane >> 2, tg = lane & 3;
    int warp_m = wid >> 2, warp_n = wid & 3;
    int m0 = blockIdx.y * TBM, n0 = blockIdx.x * TBN;

    int Keff = CAUSAL ? (m0 + TBM < K ? m0 + TBM : K) : K;
    int kTiles = Keff / TBK;

    int ar = tid >> 1, ac8 = (tid & 1) * 8;
    int br = tid >> 5, bc = (tid & 31) * 4;
    const float* Abase = A + (size_t)(m0 + ar) * lda + ac8;
    const float* Bbase = B + (size_t)br * N + n0 + bc;

    // ldmatrix per-lane offset (elements): row = (lane&7) + 8*((lane>>3)&1), kcol = 4*(lane>>4)
    unsigned asm_base = (unsigned)__cvta_generic_to_shared(Asm);
    unsigned aoff4 = (((lane & 7) + ((lane >> 3) & 1) * 8) * ASTR + ((lane >> 4) << 2)) * 4;

    float c[4][4][4];
#pragma unroll
    for (int i = 0; i < 4; i++)
#pragma unroll
        for (int j = 0; j < 4; j++)
#pragma unroll
            for (int r = 0; r < 4; r++) c[i][j][r] = 0.f;

#pragma unroll
    for (int s = 0; s < NSTG - 1; s++) {
        if (s < kTiles) {
            float* as = Asm + s * ASZ;
            float* bs = Bsm + s * BSZ;
            const float* Ap = Abase + s * TBK;
            const float* Bp = Bbase + (size_t)s * TBK * N;
            cpa16(as + ar * ASTR + ac8,     Ap);
            cpa16(as + ar * ASTR + ac8 + 4, Ap + 4);
            cpa16(bs + br * BSTR + bc,       Bp);
            cpa16(bs + (br + 8) * BSTR + bc, Bp + (size_t)8 * N);
        }
        CP_COMMIT();
    }
    CP_WAIT2();
    __syncthreads();

    int cur = 0;
    for (int t = 0; t < kTiles; t++) {
        int tp = t + NSTG - 1;
        if (tp < kTiles) {
            int ps = tp & (NSTG - 1);
            float* as = Asm + ps * ASZ;
            float* bs = Bsm + ps * BSZ;
            const float* Ap = Abase + tp * TBK;
            const float* Bp = Bbase + (size_t)tp * TBK * N;
            cpa16(as + ar * ASTR + ac8,     Ap);
            cpa16(as + ar * ASTR + ac8 + 4, Ap + 4);
            cpa16(bs + br * BSTR + bc,       Bp);
            cpa16(bs + (br + 8) * BSTR + bc, Bp + (size_t)8 * N);
        }
        CP_COMMIT();

        unsigned abase = asm_base + (unsigned)(cur * ASZ * 4) + aoff4
                       + (unsigned)((warp_m * 64) * ASTR * 4);
        float* bs = Bsm + cur * BSZ;
#pragma unroll
        for (int kc = 0; kc < TBK; kc += 8) {
            unsigned a[4][4], b[4][2];
#pragma unroll
            for (int mt = 0; mt < 4; mt++) {
                unsigned addr = abase + (unsigned)((mt * 16 * ASTR + kc) * 4);
                ldsm4(a[mt][0], a[mt][1], a[mt][2], a[mt][3], addr);
            }
#pragma unroll
            for (int nt = 0; nt < 4; nt++) {
                int n = warp_n * 32 + nt * 8 + group;
                b[nt][0] = __float_as_uint(bs[(kc + tg) * BSTR + n]);
                b[nt][1] = __float_as_uint(bs[(kc + tg + 4) * BSTR + n]);
            }
#pragma unroll
            for (int mt = 0; mt < 4; mt++)
#pragma unroll
                for (int nt = 0; nt < 4; nt++) {
                    asm volatile(
                        "mma.sync.aligned.m16n8k8.row.col.f32.tf32.tf32.f32 "
                        "{%0,%1,%2,%3}, {%4,%5,%6,%7}, {%8,%9}, {%0,%1,%2,%3};"
                        : "+f"(c[mt][nt][0]), "+f"(c[mt][nt][1]),
                          "+f"(c[mt][nt][2]), "+f"(c[mt][nt][3])
                        : "r"(a[mt][0]), "r"(a[mt][1]), "r"(a[mt][2]), "r"(a[mt][3]),
                          "r"(b[nt][0]), "r"(b[nt][1]));
                }
        }
        CP_WAIT2();
        __syncthreads();
        cur = (cur + 1) & (NSTG - 1);
    }

#pragma unroll
    for (int mt = 0; mt < 4; mt++) {
#pragma unroll
        for (int nt = 0; nt < 4; nt++) {
#pragma unroll
            for (int r = 0; r < 4; r++) {
                int m = m0 + warp_m * 64 + mt * 16 + group + (r >> 1) * 8;
                int n = n0 + warp_n * 32 + nt * 8 + tg * 2 + (r & 1);
                float v = c[mt][nt][r];
                if (EPI == 1) v = expf(fminf(fmaxf(v + bias[n], -10.f), 10.f));
                else if (EPI == 2) v = v + bias[n];
                else if (EPI == 3) v = fmaxf(v + bias[n], 0.f);
                if (ROUND) v = rnd(v);
                if (PERM == 0) {
                    C[(size_t)m * N + n] = v;
                } else {
                    int h = n & 7, inner = n >> 3;
                    C[((size_t)(h * M + m)) * (N >> 3) + inner] = v;
                }
            }
        }
    }
}

// -------- S_h = tril(Q_h K_h^T), tensor cores, 64x64 tiles --------
__global__ void __launch_bounds__(128) qks_kernel(const float* __restrict__ qh,
    const float* __restrict__ kh, float* __restrict__ S)
{
    int h = blockIdx.z;
    int m0 = blockIdx.y * 64, n0 = blockIdx.x * 64;
    float* Sh = S + (size_t)h * L * L;
    int tid = threadIdx.x;

    if (n0 > m0 + 63) {
        float4 zz = make_float4(0.f, 0.f, 0.f, 0.f);
        for (int i = tid; i < 1024; i += 128) {
            int r = i >> 4, cc = (i & 15) * 4;
            *(float4*)&Sh[(size_t)(m0 + r) * L + n0 + cc] = zz;
        }
        return;
    }

    __shared__ float Qs[64][36];
    __shared__ float Ks[64][36];
    const float* Q  = qh + ((size_t)h * L + m0) * DA;
    const float* Kk = kh + ((size_t)h * L + n0) * DA;
    for (int i = tid; i < 512; i += 128) {
        int r = i >> 3, cc = (i & 7) * 4;
        *(float4*)&Qs[r][cc] = *(const float4*)&Q[r * DA + cc];
        *(float4*)&Ks[r][cc] = *(const float4*)&Kk[r * DA + cc];
    }
    __syncthreads();

    int wid = tid >> 5, lane = tid & 31;
    int group = lane >> 2, tg = lane & 3;
    int warp_m = wid >> 1, warp_n = wid & 1;

    float c[2][4][4];
#pragma unroll
    for (int i = 0; i < 2; i++)
#pragma unroll
        for (int j = 0; j < 4; j++)
#pragma unroll
            for (int r = 0; r < 4; r++) c[i][j][r] = 0.f;

#pragma unroll
    for (int kc = 0; kc < 32; kc += 8) {
        unsigned a[2][4], b[4][2];
#pragma unroll
        for (int mt = 0; mt < 2; mt++) {
            int r = warp_m * 32 + mt * 16 + group;
            a[mt][0] = __float_as_uint(Qs[r][kc + tg]);
            a[mt][1] = __float_as_uint(Qs[r + 8][kc + tg]);
            a[mt][2] = __float_as_uint(Qs[r][kc + tg + 4]);
            a[mt][3] = __float_as_uint(Qs[r + 8][kc + tg + 4]);
        }
#pragma unroll
        for (int nt = 0; nt < 4; nt++) {
            int n = warp_n * 32 + nt * 8 + group;
            b[nt][0] = __float_as_uint(Ks[n][kc + tg]);
            b[nt][1] = __float_as_uint(Ks[n][kc + tg + 4]);
        }
#pragma unroll
        for (int mt = 0; mt < 2; mt++)
#pragma unroll
            for (int nt = 0; nt < 4; nt++) {
                asm volatile(
                    "mma.sync.aligned.m16n8k8.row.col.f32.tf32.tf32.f32 "
                    "{%0,%1,%2,%3}, {%4,%5,%6,%7}, {%8,%9}, {%0,%1,%2,%3};"
                    : "+f"(c[mt][nt][0]), "+f"(c[mt][nt][1]),
                      "+f"(c[mt][nt][2]), "+f"(c[mt][nt][3])
                    : "r"(a[mt][0]), "r"(a[mt][1]), "r"(a[mt][2]), "r"(a[mt][3]),
                      "r"(b[nt][0]), "r"(b[nt][1]));
            }
    }

#pragma unroll
    for (int mt = 0; mt < 2; mt++)
#pragma unroll
        for (int nt = 0; nt < 4; nt++)
#pragma unroll
            for (int r = 0; r < 4; r++) {
                int m = m0 + warp_m * 32 + mt * 16 + group + (r >> 1) * 8;
                int n = n0 + warp_n * 32 + nt * 8 + tg * 2 + (r & 1);
                Sh[(size_t)m * L + n] = (n <= m) ? rnd(c[mt][nt][r]) : 0.f;
            }
}

__global__ void den_kernel(const float* __restrict__ S, float* __restrict__ den) {
    int l = blockIdx.x, h = blockIdx.y, tid = threadIdx.x;
    const float* row = S + ((size_t)h * L + l) * L;
    float s = 0.f;
    for (int i = tid; i <= l; i += 256) s += row[i];
    float2 r = block_reduce2(s, 0.f);
    if (tid == 0) den[h * L + l] = r.x;
}

__global__ void y_kernel(const float* __restrict__ x, const float* __restrict__ qkvh,
                         const float* __restrict__ den, const float* __restrict__ w,
                         const float* __restrict__ b, float* __restrict__ y)
{
    int l = blockIdx.x, tid = threadIdx.x;  // 512 threads
    float t[8];
    float s = 0.f, s2 = 0.f;
#pragma unroll
    for (int r = 0; r < 8; r++) {
        int j = tid + r * 512;
        int h = j & 7, d = j >> 3;
        float v = qkvh[((size_t)(h * L + l)) * D + d] / den[h * L + l];
        t[r] = v; s += v; s2 += v * v;
    }
    float2 red = block_reduce2(s, s2);
    float mu = red.x * (1.0f / DH);
    float rs = rsqrtf(red.y * (1.0f / DH) - mu * mu + 1e-5f);
#pragma unroll
    for (int r = 0; r < 8; r++) {
        int j = tid + r * 512;
        y[(size_t)l * DH + j] = rnd(x[(size_t)l * D + (j >> 3)] + (t[r] - mu) * rs * w[j] + b[j]);
    }
}

// -------- split-K reduce for h1: relu(p0+p1+b1), rounded --------
__global__ void reduce_h1(const float* __restrict__ part, const float* __restrict__ b1,
                          float* __restrict__ h1)
{
    int q = blockIdx.x * 256 + threadIdx.x;   // quads over L*FF
    const float4* p = (const float4*)part;
    float4 v0 = p[q];
    float4 v1 = p[q + (L * FF / 4)];
    float4 bb = ((const float4*)b1)[q & (FF / 4 - 1)];
    float4 o;
    o.x = rnd(fmaxf(v0.x + v1.x + bb.x, 0.f));
    o.y = rnd(fmaxf(v0.y + v1.y + bb.y, 0.f));
    o.z = rnd(fmaxf(v0.z + v1.z + bb.z, 0.f));
    o.w = rnd(fmaxf(v0.w + v1.w + bb.w, 0.f));
    ((float4*)h1)[q] = o;
}

// -------- split-K reduce + relu + bias + residual (output) --------
__global__ void reduce_out(const float* __restrict__ part, const float* __restrict__ b2,
                           const float* __restrict__ x, float* __restrict__ out)
{
    int q = blockIdx.x * 256 + threadIdx.x;
    const float4* p = (const float4*)part;
    float4 v0 = p[q];
    float4 v1 = p[q + 131072];
    float4 v2 = p[q + 262144];
    float4 v3 = p[q + 393216];
    float4 bb = ((const float4*)b2)[q & 127];
    float4 xx = ((const float4*)x)[q];
    float4 o;
    o.x = fmaxf(v0.x + v1.x + v2.x + v3.x + bb.x, 0.f) + xx.x;
    o.y = fmaxf(v0.y + v1.y + v2.y + v3.y + bb.y, 0.f) + xx.y;
    o.z = fmaxf(v0.z + v1.z + v2.z + v3.z + bb.z, 0.f) + xx.z;
    o.w = fmaxf(v0.w + v1.w + v2.w + v3.w + bb.w, 0.f) + xx.w;
    ((float4*)out)[q] = o;
}

extern "C" void kernel_launch(void* const* d_in, const int* in_sizes, int n_in,
                              void* d_out, int out_size)
{
    const float* x    = (const float*)d_in[0];
    const float* ln0w = (const float*)d_in[1];
    const float* ln0b = (const float*)d_in[2];
    const float* ln1w = (const float*)d_in[3];
    const float* ln1b = (const float*)d_in[4];
    const float* qw   = (const float*)d_in[5];
    const float* qb   = (const float*)d_in[6];
    const float* kw   = (const float*)d_in[7];
    const float* kb   = (const float*)d_in[8];
    const float* vw   = (const float*)d_in[9];
    const float* vb   = (const float*)d_in[10];
    const float* w1   = (const float*)d_in[11];
    const float* b1   = (const float*)d_in[12];
    const float* w2   = (const float*)d_in[13];
    const float* b2   = (const float*)d_in[14];
    float* out = (float*)d_out;

    float *xn, *rx, *rqw, *rkw, *rvw, *rw1, *rw2;
    float *qh, *kh, *vh, *S, *den, *qkvh, *y, *h1, *part, *parth;
    cudaGetSymbolAddress((void**)&xn,   g_xn);
    cudaGetSymbolAddress((void**)&rx,   g_rx);
    cudaGetSymbolAddress((void**)&rqw,  g_rqw);
    cudaGetSymbolAddress((void**)&rkw,  g_rkw);
    cudaGetSymbolAddress((void**)&rvw,  g_rvw);
    cudaGetSymbolAddress((void**)&rw1,  g_rw1);
    cudaGetSymbolAddress((void**)&rw2,  g_rw2);
    cudaGetSymbolAddress((void**)&qh,   g_qh);
    cudaGetSymbolAddress((void**)&kh,   g_kh);
    cudaGetSymbolAddress((void**)&vh,   g_vh);
    cudaGetSymbolAddress((void**)&S,    g_S);
    cudaGetSymbolAddress((void**)&den,  g_den);
    cudaGetSymbolAddress((void**)&qkvh, g_qkvh);
    cudaGetSymbolAddress((void**)&y,    g_y);
    cudaGetSymbolAddress((void**)&h1,   g_h1);
    cudaGetSymbolAddress((void**)&part, g_part);
    cudaGetSymbolAddress((void**)&parth, g_parth);

    cudaFuncSetAttribute(tgemm<1,1,0,1,1>, cudaFuncAttributeMaxDynamicSharedMemorySize, SMEM_BYTES);
    cudaFuncSetAttribute(tgemm<2,1,0,0,1>, cudaFuncAttributeMaxDynamicSharedMemorySize, SMEM_BYTES);
    cudaFuncSetAttribute(tgemm<0,0,1,0,0>, cudaFuncAttributeMaxDynamicSharedMemorySize, SMEM_BYTES);
    cudaFuncSetAttribute(tgemm<0,0,0,2,0>, cudaFuncAttributeMaxDynamicSharedMemorySize, SMEM_BYTES);

    // 0) round weights + x to tf32
    round_multi<<<12032, 256>>>(qw, kw, vw, w1, w2, x, rqw, rkw, rvw, rw1, rw2, rx);
    // 1) LN0 (rounded)
    ln0_kernel<<<L, 256>>>(x, ln0w, ln0b, xn);
    // 2) q,k projections (merged, exp-clip, head-major, rounded)
    tgemm<1,1,0,1,1><<<dim3(AH/TBN, L/TBM, 2), 256, SMEM_BYTES>>>(
        xn, rqw, qb, qh, rkw, kb, kh, L, AH, D, D);
    // 3) v projection (+bias, head-major, rounded)
    tgemm<2,1,0,0,1><<<dim3(DH/TBN, L/TBM), 256, SMEM_BYTES>>>(
        rx, rvw, vb, vh, nullptr, nullptr, nullptr, L, DH, D, D);
    // 4) S = tril(QK^T) per head (tensor, rounded)
    qks_kernel<<<dim3(16, 16, NH), 128>>>(qh, kh, S);
    // 5) den = rowsum(S)
    den_kernel<<<dim3(L, NH), 256>>>(S, den);
    // 6) qkv = S @ V (batched, causal K-trim)
    tgemm<0,0,1,0,0><<<dim3(D/TBN, L/TBM, NH), 256, SMEM_BYTES>>>(
        S, vh, nullptr, qkvh, nullptr, nullptr, nullptr, L, D, L, L);
    // 7) y = x + LN1(qkv/den) (rounded)
    y_kernel<<<L, 512>>>(x, qkvh, den, ln1w, ln1b, y);
    // 8) h1 partials: splitK=2 of y@w1
    tgemm<0,0,0,2,0><<<dim3(FF/TBN, L/TBM, 2), 256, SMEM_BYTES>>>(
        y, rw1, nullptr, parth, nullptr, nullptr, nullptr, L, FF, DH/2, DH);
    // 8b) h1 = rnd(relu(sum + b1))
    reduce_h1<<<2048, 256>>>(parth, b1, h1);
    // 9) split-K=4 partials of h1@w2
    tgemm<0,0,0,2,0><<<dim3(D/TBN, L/TBM, 4), 256, SMEM_BYTES>>>(
        h1, rw2, nullptr, part, nullptr, nullptr, nullptr, L, D, FF/4, FF);
    // 10) out = relu(sum+b2)+x
    reduce_out<<<512, 256>>>(part, b2, x, out);
}

// round 5
// speedup vs baseline: 4.5771x; 1.0924x over previous
#include <cuda_runtime.h>
#include <math.h>

#define L  1024
#define D  512
#define NH 8
#define DA 32
#define AH 256
#define DH 4096
#define FF 2048

// -------- scratch --------
__device__ float g_xn[L * D];
__device__ float g_rx[L * D];
__device__ float g_rqw[D * AH];
__device__ float g_rkw[D * AH];
__device__ float g_rvw[D * DH];
__device__ float g_rw1[DH * FF];
__device__ float g_rw2[FF * D];
__device__ float g_qh[NH * L * DA];
__device__ float g_kh[NH * L * DA];
__device__ float g_vh[NH * L * D];
__device__ float g_S[(size_t)NH * L * L];
__device__ float g_den[NH * L];
__device__ float g_qkvh[NH * L * D];
__device__ float g_y[(size_t)L * DH];
__device__ float g_h1[L * FF];
__device__ float g_part[4 * L * D];
__device__ float g_parth[2 * L * FF];
__device__ float g_partq[4 * L * AH];
__device__ float g_partk[4 * L * AH];

__device__ __forceinline__ unsigned f2tf32(float v) {
    unsigned o;
    asm volatile("cvt.rna.tf32.f32 %0, %1;" : "=r"(o) : "f"(v));
    return o;
}
__device__ __forceinline__ float rnd(float v) { return __uint_as_float(f2tf32(v)); }

__device__ __forceinline__ void cpa16(void* s, const void* g) {
    unsigned sa = (unsigned)__cvta_generic_to_shared(s);
    asm volatile("cp.async.cg.shared.global [%0], [%1], 16;\n" :: "r"(sa), "l"(g));
}
#define CP_COMMIT() asm volatile("cp.async.commit_group;\n" ::: "memory")
#define CP_WAIT2()  asm volatile("cp.async.wait_group 2;\n" ::: "memory")

__device__ __forceinline__ void ldsm4(unsigned& r0, unsigned& r1, unsigned& r2, unsigned& r3,
                                      unsigned addr) {
    asm volatile("ldmatrix.sync.aligned.m8n8.x4.shared.b16 {%0,%1,%2,%3}, [%4];"
                 : "=r"(r0), "=r"(r1), "=r"(r2), "=r"(r3) : "r"(addr));
}

__device__ __forceinline__ float2 block_reduce2(float a, float b) {
    __shared__ float2 sh[16];
    int tid = threadIdx.x;
#pragma unroll
    for (int o = 16; o > 0; o >>= 1) {
        a += __shfl_down_sync(0xffffffffu, a, o);
        b += __shfl_down_sync(0xffffffffu, b, o);
    }
    int wid = tid >> 5, lane = tid & 31;
    int nw = blockDim.x >> 5;
    if (lane == 0) sh[wid] = make_float2(a, b);
    __syncthreads();
    if (wid == 0) {
        float2 v = (lane < nw) ? sh[lane] : make_float2(0.f, 0.f);
        a = v.x; b = v.y;
#pragma unroll
        for (int o = 8; o > 0; o >>= 1) {
            a += __shfl_down_sync(0xffffffffu, a, o);
            b += __shfl_down_sync(0xffffffffu, b, o);
        }
        if (lane == 0) sh[0] = make_float2(a, b);
    }
    __syncthreads();
    return sh[0];
}

// -------- one-shot tf32 rounding of weights + x --------
__global__ void round_multi(const float* __restrict__ qw, const float* __restrict__ kw,
                            const float* __restrict__ vw, const float* __restrict__ w1,
                            const float* __restrict__ w2, const float* __restrict__ x,
                            float* rqw, float* rkw, float* rvw, float* rw1, float* rw2, float* rx)
{
    int q = blockIdx.x * 256 + threadIdx.x;
    const float4* s; float4* d; int off;
    if (q < 32768)        { s = (const float4*)qw; d = (float4*)rqw; off = q; }
    else if (q < 65536)   { s = (const float4*)kw; d = (float4*)rkw; off = q - 32768; }
    else if (q < 589824)  { s = (const float4*)vw; d = (float4*)rvw; off = q - 65536; }
    else if (q < 2686976) { s = (const float4*)w1; d = (float4*)rw1; off = q - 589824; }
    else if (q < 2949120) { s = (const float4*)w2; d = (float4*)rw2; off = q - 2686976; }
    else                  { s = (const float4*)x;  d = (float4*)rx;  off = q - 2949120; }
    float4 v = s[off];
    v.x = rnd(v.x); v.y = rnd(v.y); v.z = rnd(v.z); v.w = rnd(v.w);
    d[off] = v;
}

__global__ void ln0_kernel(const float* __restrict__ x, const float* __restrict__ w,
                           const float* __restrict__ b, float* __restrict__ out) {
    int l = blockIdx.x, tid = threadIdx.x;
    const float* row = x + (size_t)l * D;
    float v0 = row[tid], v1 = row[tid + 256];
    float2 r = block_reduce2(v0 + v1, v0 * v0 + v1 * v1);
    float mu = r.x * (1.0f / D);
    float var = r.y * (1.0f / D) - mu * mu;
    float rs = rsqrtf(var + 1e-5f);
    out[(size_t)l * D + tid]       = rnd((v0 - mu) * rs * w[tid]       + b[tid]);
    out[(size_t)l * D + tid + 256] = rnd((v1 - mu) * rs * w[tid + 256] + b[tid + 256]);
}

// ================= tf32 tensor GEMM: 128x128 CTA, 4 warps, warp 64x64 =================
#define TBM 128
#define TBN 128
#define TBK 16
#define NSTG 4
#define ASTR 20
#define BSTR 136
#define ASZ (TBM * ASTR)
#define BSZ (TBK * BSTR)
#define SMEM_BYTES ((NSTG * (ASZ + BSZ)) * 4)

// EPI: 0 none, 1 exp(clip(+bias)), 2 +bias, 3 relu(+bias)
// MODE: 0 batched-by-z, 2 splitK
template<int EPI, int PERM, int CAUSAL, int MODE, int ROUND>
__global__ void __launch_bounds__(128, 2) tgemm(
    const float* __restrict__ A, const float* __restrict__ B,
    const float* __restrict__ bias, float* __restrict__ C,
    int M, int N, int K, int lda)
{
    extern __shared__ float smem[];
    float* Asm = smem;
    float* Bsm = smem + NSTG * ASZ;

    int z = blockIdx.z;
    if (MODE == 0) {
        A += (size_t)z * M * lda;
        B += (size_t)z * K * N;
        C += (size_t)z * M * N;
    } else if (MODE == 2) {
        A += (size_t)z * K;
        B += (size_t)z * K * N;
        C += (size_t)z * M * N;
    }

    int tid = threadIdx.x;
    int wid = tid >> 5, lane = tid & 31;
    int group = lane >> 2, tg = lane & 3;
    int warp_m = wid >> 1, warp_n = wid & 1;   // 2x2, warp tile 64x64
    int m0 = blockIdx.y * TBM, n0 = blockIdx.x * TBN;

    int Keff = CAUSAL ? (m0 + TBM < K ? m0 + TBM : K) : K;
    int kTiles = Keff / TBK;

    // global load addressing (128 threads): A 4 cpa, B 4 cpa per stage
    int ar = tid >> 1, ac8 = (tid & 1) * 8;
    int br = tid >> 5, bc = (tid & 31) * 4;
    const float* Abase = A + (size_t)(m0 + ar) * lda + ac8;
    const float* Bbase = B + (size_t)br * N + n0 + bc;

    unsigned asm_base = (unsigned)__cvta_generic_to_shared(Asm);
    unsigned aoff4 = (((lane & 7) + ((lane >> 3) & 1) * 8) * ASTR + ((lane >> 4) << 2)) * 4;

    float c[4][8][4];
#pragma unroll
    for (int i = 0; i < 4; i++)
#pragma unroll
        for (int j = 0; j < 8; j++)
#pragma unroll
            for (int r = 0; r < 4; r++) c[i][j][r] = 0.f;

#pragma unroll
    for (int s = 0; s < NSTG - 1; s++) {
        if (s < kTiles) {
            float* as = Asm + s * ASZ;
            float* bs = Bsm + s * BSZ;
            const float* Ap = Abase + s * TBK;
            const float* Bp = Bbase + (size_t)s * TBK * N;
            cpa16(as + ar * ASTR + ac8,            Ap);
            cpa16(as + ar * ASTR + ac8 + 4,        Ap + 4);
            cpa16(as + (ar + 64) * ASTR + ac8,     Ap + (size_t)64 * lda);
            cpa16(as + (ar + 64) * ASTR + ac8 + 4, Ap + (size_t)64 * lda + 4);
            cpa16(bs + br * BSTR + bc,        Bp);
            cpa16(bs + (br + 4) * BSTR + bc,  Bp + (size_t)4 * N);
            cpa16(bs + (br + 8) * BSTR + bc,  Bp + (size_t)8 * N);
            cpa16(bs + (br + 12) * BSTR + bc, Bp + (size_t)12 * N);
        }
        CP_COMMIT();
    }
    CP_WAIT2();
    __syncthreads();

    int cur = 0;
    for (int t = 0; t < kTiles; t++) {
        int tp = t + NSTG - 1;
        if (tp < kTiles) {
            int ps = tp & (NSTG - 1);
            float* as = Asm + ps * ASZ;
            float* bs = Bsm + ps * BSZ;
            const float* Ap = Abase + tp * TBK;
            const float* Bp = Bbase + (size_t)tp * TBK * N;
            cpa16(as + ar * ASTR + ac8,            Ap);
            cpa16(as + ar * ASTR + ac8 + 4,        Ap + 4);
            cpa16(as + (ar + 64) * ASTR + ac8,     Ap + (size_t)64 * lda);
            cpa16(as + (ar + 64) * ASTR + ac8 + 4, Ap + (size_t)64 * lda + 4);
            cpa16(bs + br * BSTR + bc,        Bp);
            cpa16(bs + (br + 4) * BSTR + bc,  Bp + (size_t)4 * N);
            cpa16(bs + (br + 8) * BSTR + bc,  Bp + (size_t)8 * N);
            cpa16(bs + (br + 12) * BSTR + bc, Bp + (size_t)12 * N);
        }
        CP_COMMIT();

        unsigned abase = asm_base + (unsigned)(cur * ASZ * 4) + aoff4
                       + (unsigned)((warp_m * 64) * ASTR * 4);
        float* bs = Bsm + cur * BSZ;

        // load all fragments for the tile (both kc chunks), then issue MMAs
        unsigned a[2][4][4], b[2][8][2];
#pragma unroll
        for (int kk = 0; kk < 2; kk++) {
#pragma unroll
            for (int mt = 0; mt < 4; mt++) {
                unsigned addr = abase + (unsigned)((mt * 16 * ASTR + kk * 8) * 4);
                ldsm4(a[kk][mt][0], a[kk][mt][1], a[kk][mt][2], a[kk][mt][3], addr);
            }
#pragma unroll
            for (int nt = 0; nt < 8; nt++) {
                int n = warp_n * 64 + nt * 8 + group;
                b[kk][nt][0] = __float_as_uint(bs[(kk * 8 + tg) * BSTR + n]);
                b[kk][nt][1] = __float_as_uint(bs[(kk * 8 + tg + 4) * BSTR + n]);
            }
        }
#pragma unroll
        for (int kk = 0; kk < 2; kk++)
#pragma unroll
            for (int mt = 0; mt < 4; mt++)
#pragma unroll
                for (int nt = 0; nt < 8; nt++) {
                    asm volatile(
                        "mma.sync.aligned.m16n8k8.row.col.f32.tf32.tf32.f32 "
                        "{%0,%1,%2,%3}, {%4,%5,%6,%7}, {%8,%9}, {%0,%1,%2,%3};"
                        : "+f"(c[mt][nt][0]), "+f"(c[mt][nt][1]),
                          "+f"(c[mt][nt][2]), "+f"(c[mt][nt][3])
                        : "r"(a[kk][mt][0]), "r"(a[kk][mt][1]),
                          "r"(a[kk][mt][2]), "r"(a[kk][mt][3]),
                          "r"(b[kk][nt][0]), "r"(b[kk][nt][1]));
                }

        CP_WAIT2();
        __syncthreads();
        cur = (cur + 1) & (NSTG - 1);
    }

#pragma unroll
    for (int mt = 0; mt < 4; mt++) {
#pragma unroll
        for (int nt = 0; nt < 8; nt++) {
#pragma unroll
            for (int r = 0; r < 4; r++) {
                int m = m0 + warp_m * 64 + mt * 16 + group + (r >> 1) * 8;
                int n = n0 + warp_n * 64 + nt * 8 + tg * 2 + (r & 1);
                float v = c[mt][nt][r];
                if (EPI == 1) v = expf(fminf(fmaxf(v + bias[n], -10.f), 10.f));
                else if (EPI == 2) v = v + bias[n];
                else if (EPI == 3) v = fmaxf(v + bias[n], 0.f);
                if (ROUND) v = rnd(v);
                if (PERM == 0) {
                    C[(size_t)m * N + n] = v;
                } else {
                    int h = n & 7, inner = n >> 3;
                    C[((size_t)(h * M + m)) * (N >> 3) + inner] = v;
                }
            }
        }
    }
}

// -------- split-K reduce for q/k: exp(clip(sum+bias)), head-major, rounded --------
__global__ void reduce_qk(const float* __restrict__ pq, const float* __restrict__ pk,
                          const float* __restrict__ qb, const float* __restrict__ kb,
                          float* __restrict__ qh, float* __restrict__ kh)
{
    int set = blockIdx.y;
    const float* p   = set ? pk : pq;
    const float* bia = set ? kb : qb;
    float* o = set ? kh : qh;
    int i = blockIdx.x * 256 + threadIdx.x;   // over L*AH = 262144
    int m = i >> 8, n = i & 255;
    float s = p[i] + p[i + 262144] + p[i + 524288] + p[i + 786432] + bia[n];
    s = rnd(expf(fminf(fmaxf(s, -10.f), 10.f)));
    int h = n & 7, inner = n >> 3;
    o[((size_t)(h * L + m)) * DA + inner] = s;
}

// -------- S_h = tril(Q_h K_h^T), tensor cores, 64x64 tiles --------
__global__ void __launch_bounds__(128) qks_kernel(const float* __restrict__ qh,
    const float* __restrict__ kh, float* __restrict__ S)
{
    int h = blockIdx.z;
    int m0 = blockIdx.y * 64, n0 = blockIdx.x * 64;
    float* Sh = S + (size_t)h * L * L;
    int tid = threadIdx.x;

    if (n0 > m0 + 63) {
        float4 zz = make_float4(0.f, 0.f, 0.f, 0.f);
        for (int i = tid; i < 1024; i += 128) {
            int r = i >> 4, cc = (i & 15) * 4;
            *(float4*)&Sh[(size_t)(m0 + r) * L + n0 + cc] = zz;
        }
        return;
    }

    __shared__ float Qs[64][36];
    __shared__ float Ks[64][36];
    const float* Q  = qh + ((size_t)h * L + m0) * DA;
    const float* Kk = kh + ((size_t)h * L + n0) * DA;
    for (int i = tid; i < 512; i += 128) {
        int r = i >> 3, cc = (i & 7) * 4;
        *(float4*)&Qs[r][cc] = *(const float4*)&Q[r * DA + cc];
        *(float4*)&Ks[r][cc] = *(const float4*)&Kk[r * DA + cc];
    }
    __syncthreads();

    int wid = tid >> 5, lane = tid & 31;
    int group = lane >> 2, tg = lane & 3;
    int warp_m = wid >> 1, warp_n = wid & 1;

    float c[2][4][4];
#pragma unroll
    for (int i = 0; i < 2; i++)
#pragma unroll
        for (int j = 0; j < 4; j++)
#pragma unroll
            for (int r = 0; r < 4; r++) c[i][j][r] = 0.f;

#pragma unroll
    for (int kc = 0; kc < 32; kc += 8) {
        unsigned a[2][4], b[4][2];
#pragma unroll
        for (int mt = 0; mt < 2; mt++) {
            int r = warp_m * 32 + mt * 16 + group;
            a[mt][0] = __float_as_uint(Qs[r][kc + tg]);
            a[mt][1] = __float_as_uint(Qs[r + 8][kc + tg]);
            a[mt][2] = __float_as_uint(Qs[r][kc + tg + 4]);
            a[mt][3] = __float_as_uint(Qs[r + 8][kc + tg + 4]);
        }
#pragma unroll
        for (int nt = 0; nt < 4; nt++) {
            int n = warp_n * 32 + nt * 8 + group;
            b[nt][0] = __float_as_uint(Ks[n][kc + tg]);
            b[nt][1] = __float_as_uint(Ks[n][kc + tg + 4]);
        }
#pragma unroll
        for (int mt = 0; mt < 2; mt++)
#pragma unroll
            for (int nt = 0; nt < 4; nt++) {
                asm volatile(
                    "mma.sync.aligned.m16n8k8.row.col.f32.tf32.tf32.f32 "
                    "{%0,%1,%2,%3}, {%4,%5,%6,%7}, {%8,%9}, {%0,%1,%2,%3};"
                    : "+f"(c[mt][nt][0]), "+f"(c[mt][nt][1]),
                      "+f"(c[mt][nt][2]), "+f"(c[mt][nt][3])
                    : "r"(a[mt][0]), "r"(a[mt][1]), "r"(a[mt][2]), "r"(a[mt][3]),
                      "r"(b[nt][0]), "r"(b[nt][1]));
            }
    }

#pragma unroll
    for (int mt = 0; mt < 2; mt++)
#pragma unroll
        for (int nt = 0; nt < 4; nt++)
#pragma unroll
            for (int r = 0; r < 4; r++) {
                int m = m0 + warp_m * 32 + mt * 16 + group + (r >> 1) * 8;
                int n = n0 + warp_n * 32 + nt * 8 + tg * 2 + (r & 1);
                Sh[(size_t)m * L + n] = (n <= m) ? rnd(c[mt][nt][r]) : 0.f;
            }
}

__global__ void den_kernel(const float* __restrict__ S, float* __restrict__ den) {
    int l = blockIdx.x, h = blockIdx.y, tid = threadIdx.x;
    const float* row = S + ((size_t)h * L + l) * L;
    float s = 0.f;
    for (int i = tid; i <= l; i += 256) s += row[i];
    float2 r = block_reduce2(s, 0.f);
    if (tid == 0) den[h * L + l] = r.x;
}

__global__ void y_kernel(const float* __restrict__ x, const float* __restrict__ qkvh,
                         const float* __restrict__ den, const float* __restrict__ w,
                         const float* __restrict__ b, float* __restrict__ y)
{
    int l = blockIdx.x, tid = threadIdx.x;  // 512 threads
    float t[8];
    float s = 0.f, s2 = 0.f;
#pragma unroll
    for (int r = 0; r < 8; r++) {
        int j = tid + r * 512;
        int h = j & 7, d = j >> 3;
        float v = qkvh[((size_t)(h * L + l)) * D + d] / den[h * L + l];
        t[r] = v; s += v; s2 += v * v;
    }
    float2 red = block_reduce2(s, s2);
    float mu = red.x * (1.0f / DH);
    float rs = rsqrtf(red.y * (1.0f / DH) - mu * mu + 1e-5f);
#pragma unroll
    for (int r = 0; r < 8; r++) {
        int j = tid + r * 512;
        y[(size_t)l * DH + j] = rnd(x[(size_t)l * D + (j >> 3)] + (t[r] - mu) * rs * w[j] + b[j]);
    }
}

__global__ void reduce_h1(const float* __restrict__ part, const float* __restrict__ b1,
                          float* __restrict__ h1)
{
    int q = blockIdx.x * 256 + threadIdx.x;
    const float4* p = (const float4*)part;
    float4 v0 = p[q];
    float4 v1 = p[q + (L * FF / 4)];
    float4 bb = ((const float4*)b1)[q & (FF / 4 - 1)];
    float4 o;
    o.x = rnd(fmaxf(v0.x + v1.x + bb.x, 0.f));
    o.y = rnd(fmaxf(v0.y + v1.y + bb.y, 0.f));
    o.z = rnd(fmaxf(v0.z + v1.z + bb.z, 0.f));
    o.w = rnd(fmaxf(v0.w + v1.w + bb.w, 0.f));
    ((float4*)h1)[q] = o;
}

__global__ void reduce_out(const float* __restrict__ part, const float* __restrict__ b2,
                           const float* __restrict__ x, float* __restrict__ out)
{
    int q = blockIdx.x * 256 + threadIdx.x;
    const float4* p = (const float4*)part;
    float4 v0 = p[q];
    float4 v1 = p[q + 131072];
    float4 v2 = p[q + 262144];
    float4 v3 = p[q + 393216];
    float4 bb = ((const float4*)b2)[q & 127];
    float4 xx = ((const float4*)x)[q];
    float4 o;
    o.x = fmaxf(v0.x + v1.x + v2.x + v3.x + bb.x, 0.f) + xx.x;
    o.y = fmaxf(v0.y + v1.y + v2.y + v3.y + bb.y, 0.f) + xx.y;
    o.z = fmaxf(v0.z + v1.z + v2.z + v3.z + bb.z, 0.f) + xx.z;
    o.w = fmaxf(v0.w + v1.w + v2.w + v3.w + bb.w, 0.f) + xx.w;
    ((float4*)out)[q] = o;
}

extern "C" void kernel_launch(void* const* d_in, const int* in_sizes, int n_in,
                              void* d_out, int out_size)
{
    const float* x    = (const float*)d_in[0];
    const float* ln0w = (const float*)d_in[1];
    const float* ln0b = (const float*)d_in[2];
    const float* ln1w = (const float*)d_in[3];
    const float* ln1b = (const float*)d_in[4];
    const float* qw   = (const float*)d_in[5];
    const float* qb   = (const float*)d_in[6];
    const float* kw   = (const float*)d_in[7];
    const float* kb   = (const float*)d_in[8];
    const float* vw   = (const float*)d_in[9];
    const float* vb   = (const float*)d_in[10];
    const float* w1   = (const float*)d_in[11];
    const float* b1   = (const float*)d_in[12];
    const float* w2   = (const float*)d_in[13];
    const float* b2   = (const float*)d_in[14];
    float* out = (float*)d_out;

    float *xn, *rx, *rqw, *rkw, *rvw, *rw1, *rw2;
    float *qh, *kh, *vh, *S, *den, *qkvh, *y, *h1, *part, *parth, *partq, *partk;
    cudaGetSymbolAddress((void**)&xn,    g_xn);
    cudaGetSymbolAddress((void**)&rx,    g_rx);
    cudaGetSymbolAddress((void**)&rqw,   g_rqw);
    cudaGetSymbolAddress((void**)&rkw,   g_rkw);
    cudaGetSymbolAddress((void**)&rvw,   g_rvw);
    cudaGetSymbolAddress((void**)&rw1,   g_rw1);
    cudaGetSymbolAddress((void**)&rw2,   g_rw2);
    cudaGetSymbolAddress((void**)&qh,    g_qh);
    cudaGetSymbolAddress((void**)&kh,    g_kh);
    cudaGetSymbolAddress((void**)&vh,    g_vh);
    cudaGetSymbolAddress((void**)&S,     g_S);
    cudaGetSymbolAddress((void**)&den,   g_den);
    cudaGetSymbolAddress((void**)&qkvh,  g_qkvh);
    cudaGetSymbolAddress((void**)&y,     g_y);
    cudaGetSymbolAddress((void**)&h1,    g_h1);
    cudaGetSymbolAddress((void**)&part,  g_part);
    cudaGetSymbolAddress((void**)&parth, g_parth);
    cudaGetSymbolAddress((void**)&partq, g_partq);
    cudaGetSymbolAddress((void**)&partk, g_partk);

    cudaFuncSetAttribute(tgemm<2,1,0,0,1>, cudaFuncAttributeMaxDynamicSharedMemorySize, SMEM_BYTES);
    cudaFuncSetAttribute(tgemm<0,0,1,0,0>, cudaFuncAttributeMaxDynamicSharedMemorySize, SMEM_BYTES);
    cudaFuncSetAttribute(tgemm<0,0,0,2,0>, cudaFuncAttributeMaxDynamicSharedMemorySize, SMEM_BYTES);

    // 0) round weights + x to tf32
    round_multi<<<12032, 256>>>(qw, kw, vw, w1, w2, x, rqw, rkw, rvw, rw1, rw2, rx);
    // 1) LN0 (rounded)
    ln0_kernel<<<L, 256>>>(x, ln0w, ln0b, xn);
    // 2) q,k projection partials (splitK=4 each)
    tgemm<0,0,0,2,0><<<dim3(AH/TBN, L/TBM, 4), 128, SMEM_BYTES>>>(
        xn, rqw, nullptr, partq, L, AH, D/4, D);
    tgemm<0,0,0,2,0><<<dim3(AH/TBN, L/TBM, 4), 128, SMEM_BYTES>>>(
        xn, rkw, nullptr, partk, L, AH, D/4, D);
    // 2b) q,k = rnd(exp(clip(sum+bias))), head-major
    reduce_qk<<<dim3(1024, 2), 256>>>(partq, partk, qb, kb, qh, kh);
    // 3) v projection (+bias, head-major, rounded)
    tgemm<2,1,0,0,1><<<dim3(DH/TBN, L/TBM), 128, SMEM_BYTES>>>(
        rx, rvw, vb, vh, L, DH, D, D);
    // 4) S = tril(QK^T) per head
    qks_kernel<<<dim3(16, 16, NH), 128>>>(qh, kh, S);
    // 5) den = rowsum(S)
    den_kernel<<<dim3(L, NH), 256>>>(S, den);
    // 6) qkv = S @ V (batched, causal K-trim)
    tgemm<0,0,1,0,0><<<dim3(D/TBN, L/TBM, NH), 128, SMEM_BYTES>>>(
        S, vh, nullptr, qkvh, L, D, L, L);
    // 7) y = x + LN1(qkv/den) (rounded)
    y_kernel<<<L, 512>>>(x, qkvh, den, ln1w, ln1b, y);
    // 8) h1 partials: splitK=2 of y@w1
    tgemm<0,0,0,2,0><<<dim3(FF/TBN, L/TBM, 2), 128, SMEM_BYTES>>>(
        y, rw1, nullptr, parth, L, FF, DH/2, DH);
    // 8b) h1 = rnd(relu(sum + b1))
    reduce_h1<<<2048, 256>>>(parth, b1, h1);
    // 9) split-K=4 partials of h1@w2
    tgemm<0,0,0,2,0><<<dim3(D/TBN, L/TBM, 4), 128, SMEM_BYTES>>>(
        h1, rw2, nullptr, part, L, D, FF/4, FF);
    // 10) out = relu(sum+b2)+x
    reduce_out<<<512, 256>>>(part, b2, x, out);
}

// round 6
// speedup vs baseline: 4.8147x; 1.0519x over previous
#include <cuda_runtime.h>
#include <math.h>

#define L  1024
#define D  512
#define NH 8
#define DA 32
#define AH 256
#define DH 4096
#define FF 2048

// -------- scratch --------
__device__ float g_xn[L * D];
__device__ float g_rx[L * D];
__device__ float g_rqw[D * AH];
__device__ float g_rkw[D * AH];
__device__ float g_rvw[D * DH];
__device__ float g_rw1[DH * FF];
__device__ float g_rw2[FF * D];
__device__ float g_qh[NH * L * DA];
__device__ float g_kh[NH * L * DA];
__device__ float g_vh[NH * L * D];
__device__ float g_den[NH * L];
__device__ float g_qkvh[NH * L * D];
__device__ float g_y[(size_t)L * DH];
__device__ float g_h1[L * FF];
__device__ float g_part[4 * L * D];
__device__ float g_parth[2 * L * FF];
__device__ float g_partq[4 * L * AH];
__device__ float g_partk[4 * L * AH];

__device__ __forceinline__ unsigned f2tf32(float v) {
    unsigned o;
    asm volatile("cvt.rna.tf32.f32 %0, %1;" : "=r"(o) : "f"(v));
    return o;
}
__device__ __forceinline__ float rnd(float v) { return __uint_as_float(f2tf32(v)); }

__device__ __forceinline__ void cpa16(void* s, const void* g) {
    unsigned sa = (unsigned)__cvta_generic_to_shared(s);
    asm volatile("cp.async.cg.shared.global [%0], [%1], 16;\n" :: "r"(sa), "l"(g));
}
#define CP_COMMIT() asm volatile("cp.async.commit_group;\n" ::: "memory")
#define CP_WAIT2()  asm volatile("cp.async.wait_group 2;\n" ::: "memory")

__device__ __forceinline__ void ldsm4(unsigned& r0, unsigned& r1, unsigned& r2, unsigned& r3,
                                      unsigned addr) {
    asm volatile("ldmatrix.sync.aligned.m8n8.x4.shared.b16 {%0,%1,%2,%3}, [%4];"
                 : "=r"(r0), "=r"(r1), "=r"(r2), "=r"(r3) : "r"(addr));
}

#define MMA_TF32(c0,c1,c2,c3,a0,a1,a2,a3,b0,b1) \
    asm volatile("mma.sync.aligned.m16n8k8.row.col.f32.tf32.tf32.f32 " \
        "{%0,%1,%2,%3}, {%4,%5,%6,%7}, {%8,%9}, {%0,%1,%2,%3};" \
        : "+f"(c0), "+f"(c1), "+f"(c2), "+f"(c3) \
        : "r"(a0), "r"(a1), "r"(a2), "r"(a3), "r"(b0), "r"(b1))

__device__ __forceinline__ float2 block_reduce2(float a, float b) {
    __shared__ float2 sh[16];
    int tid = threadIdx.x;
#pragma unroll
    for (int o = 16; o > 0; o >>= 1) {
        a += __shfl_down_sync(0xffffffffu, a, o);
        b += __shfl_down_sync(0xffffffffu, b, o);
    }
    int wid = tid >> 5, lane = tid & 31;
    int nw = blockDim.x >> 5;
    if (lane == 0) sh[wid] = make_float2(a, b);
    __syncthreads();
    if (wid == 0) {
        float2 v = (lane < nw) ? sh[lane] : make_float2(0.f, 0.f);
        a = v.x; b = v.y;
#pragma unroll
        for (int o = 8; o > 0; o >>= 1) {
            a += __shfl_down_sync(0xffffffffu, a, o);
            b += __shfl_down_sync(0xffffffffu, b, o);
        }
        if (lane == 0) sh[0] = make_float2(a, b);
    }
    __syncthreads();
    return sh[0];
}

// -------- one-shot tf32 rounding of weights + x --------
__global__ void round_multi(const float* __restrict__ qw, const float* __restrict__ kw,
                            const float* __restrict__ vw, const float* __restrict__ w1,
                            const float* __restrict__ w2, const float* __restrict__ x,
                            float* rqw, float* rkw, float* rvw, float* rw1, float* rw2, float* rx)
{
    int q = blockIdx.x * 256 + threadIdx.x;
    const float4* s; float4* d; int off;
    if (q < 32768)        { s = (const float4*)qw; d = (float4*)rqw; off = q; }
    else if (q < 65536)   { s = (const float4*)kw; d = (float4*)rkw; off = q - 32768; }
    else if (q < 589824)  { s = (const float4*)vw; d = (float4*)rvw; off = q - 65536; }
    else if (q < 2686976) { s = (const float4*)w1; d = (float4*)rw1; off = q - 589824; }
    else if (q < 2949120) { s = (const float4*)w2; d = (float4*)rw2; off = q - 2686976; }
    else                  { s = (const float4*)x;  d = (float4*)rx;  off = q - 2949120; }
    float4 v = s[off];
    v.x = rnd(v.x); v.y = rnd(v.y); v.z = rnd(v.z); v.w = rnd(v.w);
    d[off] = v;
}

__global__ void ln0_kernel(const float* __restrict__ x, const float* __restrict__ w,
                           const float* __restrict__ b, float* __restrict__ out) {
    int l = blockIdx.x, tid = threadIdx.x;
    const float* row = x + (size_t)l * D;
    float v0 = row[tid], v1 = row[tid + 256];
    float2 r = block_reduce2(v0 + v1, v0 * v0 + v1 * v1);
    float mu = r.x * (1.0f / D);
    float var = r.y * (1.0f / D) - mu * mu;
    float rs = rsqrtf(var + 1e-5f);
    out[(size_t)l * D + tid]       = rnd((v0 - mu) * rs * w[tid]       + b[tid]);
    out[(size_t)l * D + tid + 256] = rnd((v1 - mu) * rs * w[tid + 256] + b[tid + 256]);
}

// ================= tf32 tensor GEMM: 128x128 CTA, 4 warps, warp 64x64 =================
#define TBM 128
#define TBN 128
#define TBK 16
#define NSTG 4
#define ASTR 20
#define BSTR 136
#define ASZ (TBM * ASTR)
#define BSZ (TBK * BSTR)
#define SMEM_BYTES ((NSTG * (ASZ + BSZ)) * 4)

// EPI: 0 none, 1 exp(clip(+bias)), 2 +bias, 3 relu(+bias)
// MODE: 0 batched-by-z, 2 splitK, 3 dual-splitK (z>>2 selects B/C set, z&3 k-slice)
template<int EPI, int PERM, int CAUSAL, int MODE, int ROUND>
__global__ void __launch_bounds__(128, 2) tgemm(
    const float* __restrict__ A, const float* __restrict__ B,
    const float* __restrict__ bias, float* __restrict__ C,
    const float* __restrict__ B2, float* __restrict__ C2,
    int M, int N, int K, int lda)
{
    extern __shared__ float smem[];
    float* Asm = smem;
    float* Bsm = smem + NSTG * ASZ;

    int z = blockIdx.z;
    if (MODE == 0) {
        A += (size_t)z * M * lda;
        B += (size_t)z * K * N;
        C += (size_t)z * M * N;
    } else if (MODE == 2) {
        A += (size_t)z * K;
        B += (size_t)z * K * N;
        C += (size_t)z * M * N;
    } else if (MODE == 3) {
        int set = z >> 2, zz = z & 3;
        if (set) { B = B2; C = C2; }
        A += (size_t)zz * K;
        B += (size_t)zz * K * N;
        C += (size_t)zz * M * N;
    }

    int tid = threadIdx.x;
    int wid = tid >> 5, lane = tid & 31;
    int group = lane >> 2, tg = lane & 3;
    int warp_m = wid >> 1, warp_n = wid & 1;
    int m0 = blockIdx.y * TBM, n0 = blockIdx.x * TBN;

    int Keff = CAUSAL ? (m0 + TBM < K ? m0 + TBM : K) : K;
    int kTiles = Keff / TBK;

    int ar = tid >> 1, ac8 = (tid & 1) * 8;
    int br = tid >> 5, bc = (tid & 31) * 4;
    const float* Abase = A + (size_t)(m0 + ar) * lda + ac8;
    const float* Bbase = B + (size_t)br * N + n0 + bc;

    unsigned asm_base = (unsigned)__cvta_generic_to_shared(Asm);
    unsigned aoff4 = (((lane & 7) + ((lane >> 3) & 1) * 8) * ASTR + ((lane >> 4) << 2)) * 4;

    float c[4][8][4];
#pragma unroll
    for (int i = 0; i < 4; i++)
#pragma unroll
        for (int j = 0; j < 8; j++)
#pragma unroll
            for (int r = 0; r < 4; r++) c[i][j][r] = 0.f;

#pragma unroll
    for (int s = 0; s < NSTG - 1; s++) {
        if (s < kTiles) {
            float* as = Asm + s * ASZ;
            float* bs = Bsm + s * BSZ;
            const float* Ap = Abase + s * TBK;
            const float* Bp = Bbase + (size_t)s * TBK * N;
            cpa16(as + ar * ASTR + ac8,            Ap);
            cpa16(as + ar * ASTR + ac8 + 4,        Ap + 4);
            cpa16(as + (ar + 64) * ASTR + ac8,     Ap + (size_t)64 * lda);
            cpa16(as + (ar + 64) * ASTR + ac8 + 4, Ap + (size_t)64 * lda + 4);
            cpa16(bs + br * BSTR + bc,        Bp);
            cpa16(bs + (br + 4) * BSTR + bc,  Bp + (size_t)4 * N);
            cpa16(bs + (br + 8) * BSTR + bc,  Bp + (size_t)8 * N);
            cpa16(bs + (br + 12) * BSTR + bc, Bp + (size_t)12 * N);
        }
        CP_COMMIT();
    }
    CP_WAIT2();
    __syncthreads();

    int cur = 0;
    for (int t = 0; t < kTiles; t++) {
        int tp = t + NSTG - 1;
        if (tp < kTiles) {
            int ps = tp & (NSTG - 1);
            float* as = Asm + ps * ASZ;
            float* bs = Bsm + ps * BSZ;
            const float* Ap = Abase + tp * TBK;
            const float* Bp = Bbase + (size_t)tp * TBK * N;
            cpa16(as + ar * ASTR + ac8,            Ap);
            cpa16(as + ar * ASTR + ac8 + 4,        Ap + 4);
            cpa16(as + (ar + 64) * ASTR + ac8,     Ap + (size_t)64 * lda);
            cpa16(as + (ar + 64) * ASTR + ac8 + 4, Ap + (size_t)64 * lda + 4);
            cpa16(bs + br * BSTR + bc,        Bp);
            cpa16(bs + (br + 4) * BSTR + bc,  Bp + (size_t)4 * N);
            cpa16(bs + (br + 8) * BSTR + bc,  Bp + (size_t)8 * N);
            cpa16(bs + (br + 12) * BSTR + bc, Bp + (size_t)12 * N);
        }
        CP_COMMIT();

        unsigned abase = asm_base + (unsigned)(cur * ASZ * 4) + aoff4
                       + (unsigned)((warp_m * 64) * ASTR * 4);
        float* bs = Bsm + cur * BSZ;

        unsigned a[2][4][4], b[2][8][2];
#pragma unroll
        for (int kk = 0; kk < 2; kk++) {
#pragma unroll
            for (int mt = 0; mt < 4; mt++) {
                unsigned addr = abase + (unsigned)((mt * 16 * ASTR + kk * 8) * 4);
                ldsm4(a[kk][mt][0], a[kk][mt][1], a[kk][mt][2], a[kk][mt][3], addr);
            }
#pragma unroll
            for (int nt = 0; nt < 8; nt++) {
                int n = warp_n * 64 + nt * 8 + group;
                b[kk][nt][0] = __float_as_uint(bs[(kk * 8 + tg) * BSTR + n]);
                b[kk][nt][1] = __float_as_uint(bs[(kk * 8 + tg + 4) * BSTR + n]);
            }
        }
#pragma unroll
        for (int kk = 0; kk < 2; kk++)
#pragma unroll
            for (int mt = 0; mt < 4; mt++)
#pragma unroll
                for (int nt = 0; nt < 8; nt++)
                    MMA_TF32(c[mt][nt][0], c[mt][nt][1], c[mt][nt][2], c[mt][nt][3],
                             a[kk][mt][0], a[kk][mt][1], a[kk][mt][2], a[kk][mt][3],
                             b[kk][nt][0], b[kk][nt][1]);

        CP_WAIT2();
        __syncthreads();
        cur = (cur + 1) & (NSTG - 1);
    }

#pragma unroll
    for (int mt = 0; mt < 4; mt++) {
#pragma unroll
        for (int nt = 0; nt < 8; nt++) {
#pragma unroll
            for (int r = 0; r < 4; r++) {
                int m = m0 + warp_m * 64 + mt * 16 + group + (r >> 1) * 8;
                int n = n0 + warp_n * 64 + nt * 8 + tg * 2 + (r & 1);
                float v = c[mt][nt][r];
                if (EPI == 1) v = expf(fminf(fmaxf(v + bias[n], -10.f), 10.f));
                else if (EPI == 2) v = v + bias[n];
                else if (EPI == 3) v = fmaxf(v + bias[n], 0.f);
                if (ROUND) v = rnd(v);
                if (PERM == 0) {
                    C[(size_t)m * N + n] = v;
                } else {
                    int h = n & 7, inner = n >> 3;
                    C[((size_t)(h * M + m)) * (N >> 3) + inner] = v;
                }
            }
        }
    }
}

// -------- split-K reduce for q/k: exp(clip(sum+bias)), head-major, rounded --------
__global__ void reduce_qk(const float* __restrict__ pq, const float* __restrict__ pk,
                          const float* __restrict__ qb, const float* __restrict__ kb,
                          float* __restrict__ qh, float* __restrict__ kh)
{
    int set = blockIdx.y;
    const float* p   = set ? pk : pq;
    const float* bia = set ? kb : qb;
    float* o = set ? kh : qh;
    int i = blockIdx.x * 256 + threadIdx.x;
    int m = i >> 8, n = i & 255;
    float s = p[i] + p[i + 262144] + p[i + 524288] + p[i + 786432] + bia[n];
    s = rnd(expf(fminf(fmaxf(s, -10.f), 10.f)));
    int h = n & 7, inner = n >> 3;
    o[((size_t)(h * L + m)) * DA + inner] = s;
}

// ================= fused flash attention: S=tril(QK^T) -> den, O=S@V =================
// CTA: (d-tile 64, i-block 128, head). 256 threads.
#define SQ_STR 36
#define SV_STR 72
#define SS_STR 132
#define OFF_K  4608
#define OFF_V  13824
#define OFF_S  32256
#define OFF_DN 49152
#define ATTN_SMEM ((49152 + 512) * 4)

__global__ void __launch_bounds__(256, 1) attn_kernel(
    const float* __restrict__ qhp, const float* __restrict__ khp,
    const float* __restrict__ vhp, float* __restrict__ qkvh,
    float* __restrict__ den)
{
    extern __shared__ float sm[];
    float* Qs = sm;
    float* Ks = sm + OFF_K;
    float* Vs = sm + OFF_V;
    float* Ss = sm + OFF_S;
    float* dn = sm + OFF_DN;

    int d0 = blockIdx.x * 64;
    int i  = 7 - blockIdx.y;     // heavy blocks first
    int h  = blockIdx.z;

    int tid = threadIdx.x, lane = tid & 31, wid = tid >> 5;
    int group = lane >> 2, tg = lane & 3;
    int ws_m = wid >> 2, ws_n = wid & 3;   // S warps 2x4 -> 64x32
    int wv_m = wid >> 1, wv_n = wid & 1;   // SV warps 4x2 -> 32x32

    const float* Qg = qhp + ((size_t)h * L + i * 128) * DA;
    const float* Kg = khp + (size_t)h * L * DA;
    const float* Vg = vhp + (size_t)h * L * D + d0;

    if (tid < 128) { dn[tid] = 0.f; dn[128 + tid] = 0.f; dn[256 + tid] = 0.f; dn[384 + tid] = 0.f; }

    int qr = tid >> 2, qc = (tid & 3) * 8;
    int vr = tid >> 1, vc = (tid & 1) * 32;

    // Q load (group)
    cpa16(Qs + qr * SQ_STR + qc,            Qg + qr * DA + qc);
    cpa16(Qs + qr * SQ_STR + qc + 4,        Qg + qr * DA + qc + 4);
    cpa16(Qs + (qr + 64) * SQ_STR + qc,     Qg + (qr + 64) * DA + qc);
    cpa16(Qs + (qr + 64) * SQ_STR + qc + 4, Qg + (qr + 64) * DA + qc + 4);
    CP_COMMIT();
    // K0, V0 (group)
    {
        const float* kg = Kg;
        cpa16(Ks + qr * SQ_STR + qc,            kg + qr * DA + qc);
        cpa16(Ks + qr * SQ_STR + qc + 4,        kg + qr * DA + qc + 4);
        cpa16(Ks + (qr + 64) * SQ_STR + qc,     kg + (qr + 64) * DA + qc);
        cpa16(Ks + (qr + 64) * SQ_STR + qc + 4, kg + (qr + 64) * DA + qc + 4);
        const float* vg = Vg;
#pragma unroll
        for (int kk = 0; kk < 8; kk++)
            cpa16(Vs + vr * SV_STR + vc + kk * 4, vg + (size_t)vr * D + vc + kk * 4);
    }
    CP_COMMIT();

    float oc[2][4][4];
#pragma unroll
    for (int a = 0; a < 2; a++)
#pragma unroll
        for (int b = 0; b < 4; b++)
#pragma unroll
            for (int r = 0; r < 4; r++) oc[a][b][r] = 0.f;
    float dpart[8];
#pragma unroll
    for (int a = 0; a < 8; a++) dpart[a] = 0.f;

    unsigned qsm = (unsigned)__cvta_generic_to_shared(Qs);
    unsigned ssm = (unsigned)__cvta_generic_to_shared(Ss);
    unsigned lrow4 = (((lane & 7) + ((lane >> 3) & 1) * 8));
    unsigned qbase = qsm + (unsigned)(((ws_m * 64) * SQ_STR) * 4)
                   + (unsigned)((lrow4 * SQ_STR + ((lane >> 4) << 2)) * 4);
    unsigned sbase = ssm + (unsigned)(((wv_m * 32) * SS_STR) * 4)
                   + (unsigned)((lrow4 * SS_STR + ((lane >> 4) << 2)) * 4);

    for (int j = 0; j <= i; j++) {
        int buf = j & 1;
        if (j < i) {
            int nb = buf ^ 1;
            const float* kg = Kg + (size_t)(j + 1) * 128 * DA;
            const float* vg = Vg + (size_t)(j + 1) * 128 * D;
            float* kd = Ks + nb * (128 * SQ_STR);
            float* vd = Vs + nb * (128 * SV_STR);
            cpa16(kd + qr * SQ_STR + qc,            kg + qr * DA + qc);
            cpa16(kd + qr * SQ_STR + qc + 4,        kg + qr * DA + qc + 4);
            cpa16(kd + (qr + 64) * SQ_STR + qc,     kg + (qr + 64) * DA + qc);
            cpa16(kd + (qr + 64) * SQ_STR + qc + 4, kg + (qr + 64) * DA + qc + 4);
#pragma unroll
            for (int kk = 0; kk < 8; kk++)
                cpa16(vd + vr * SV_STR + vc + kk * 4, vg + (size_t)vr * D + vc + kk * 4);
            CP_COMMIT();
            asm volatile("cp.async.wait_group 1;\n" ::: "memory");
        } else {
            asm volatile("cp.async.wait_group 0;\n" ::: "memory");
        }
        __syncthreads();

        // ---- S = Q K_j^T ----
        float sc[4][4][4];
#pragma unroll
        for (int a = 0; a < 4; a++)
#pragma unroll
            for (int b = 0; b < 4; b++)
#pragma unroll
                for (int r = 0; r < 4; r++) sc[a][b][r] = 0.f;

        const float* ks = Ks + buf * (128 * SQ_STR);
#pragma unroll
        for (int kc = 0; kc < 32; kc += 8) {
            unsigned qa[4][4], kb[4][2];
#pragma unroll
            for (int mt = 0; mt < 4; mt++)
                ldsm4(qa[mt][0], qa[mt][1], qa[mt][2], qa[mt][3],
                      qbase + (unsigned)((mt * 16 * SQ_STR + kc) * 4));
#pragma unroll
            for (int nt = 0; nt < 4; nt++) {
                int n = ws_n * 32 + nt * 8 + group;
                kb[nt][0] = __float_as_uint(ks[n * SQ_STR + kc + tg]);
                kb[nt][1] = __float_as_uint(ks[n * SQ_STR + kc + tg + 4]);
            }
#pragma unroll
            for (int mt = 0; mt < 4; mt++)
#pragma unroll
                for (int nt = 0; nt < 4; nt++)
                    MMA_TF32(sc[mt][nt][0], sc[mt][nt][1], sc[mt][nt][2], sc[mt][nt][3],
                             qa[mt][0], qa[mt][1], qa[mt][2], qa[mt][3],
                             kb[nt][0], kb[nt][1]);
        }

        // ---- mask / rnd / den-partials / stage S to smem ----
        bool diag = (j == i);
#pragma unroll
        for (int mt = 0; mt < 4; mt++) {
#pragma unroll
            for (int rp = 0; rp < 2; rp++) {
                int row = ws_m * 64 + mt * 16 + group + rp * 8;
#pragma unroll
                for (int nt = 0; nt < 4; nt++) {
                    int colb = ws_n * 32 + nt * 8 + tg * 2;
                    float v0 = sc[mt][nt][rp * 2], v1 = sc[mt][nt][rp * 2 + 1];
                    if (diag) {
                        if (colb > row) v0 = 0.f;
                        if (colb + 1 > row) v1 = 0.f;
                    }
                    v0 = rnd(v0); v1 = rnd(v1);
                    dpart[mt * 2 + rp] += v0 + v1;
                    *(float2*)&Ss[row * SS_STR + colb] = make_float2(v0, v1);
                }
            }
        }
        __syncthreads();

        // ---- O += S @ V_j ----
        const float* vs = Vs + buf * (128 * SV_STR);
#pragma unroll
        for (int kc = 0; kc < 128; kc += 8) {
            unsigned sa[2][4], vb[4][2];
#pragma unroll
            for (int mt = 0; mt < 2; mt++)
                ldsm4(sa[mt][0], sa[mt][1], sa[mt][2], sa[mt][3],
                      sbase + (unsigned)((mt * 16 * SS_STR + kc) * 4));
#pragma unroll
            for (int nt = 0; nt < 4; nt++) {
                int n = wv_n * 32 + nt * 8 + group;
                vb[nt][0] = __float_as_uint(vs[(kc + tg) * SV_STR + n]);
                vb[nt][1] = __float_as_uint(vs[(kc + tg + 4) * SV_STR + n]);
            }
#pragma unroll
            for (int mt = 0; mt < 2; mt++)
#pragma unroll
                for (int nt = 0; nt < 4; nt++)
                    MMA_TF32(oc[mt][nt][0], oc[mt][nt][1], oc[mt][nt][2], oc[mt][nt][3],
                             sa[mt][0], sa[mt][1], sa[mt][2], sa[mt][3],
                             vb[nt][0], vb[nt][1]);
        }
        __syncthreads();
    }

    // ---- write O ----
#pragma unroll
    for (int mt = 0; mt < 2; mt++)
#pragma unroll
        for (int rp = 0; rp < 2; rp++) {
            int m = i * 128 + wv_m * 32 + mt * 16 + group + rp * 8;
#pragma unroll
            for (int nt = 0; nt < 4; nt++) {
                int dd = d0 + wv_n * 32 + nt * 8 + tg * 2;
                *(float2*)&qkvh[((size_t)h * L + m) * D + dd] =
                    make_float2(oc[mt][nt][rp * 2], oc[mt][nt][rp * 2 + 1]);
            }
        }

    // ---- den: quad-reduce then per-warp slot, deterministic final sum ----
#pragma unroll
    for (int q = 0; q < 8; q++) {
        float v = dpart[q];
        v += __shfl_xor_sync(0xffffffffu, v, 1, 4);
        v += __shfl_xor_sync(0xffffffffu, v, 2, 4);
        dpart[q] = v;
    }
    if (tg == 0) {
#pragma unroll
        for (int mt = 0; mt < 4; mt++)
#pragma unroll
            for (int rp = 0; rp < 2; rp++) {
                int row = ws_m * 64 + mt * 16 + group + rp * 8;
                dn[ws_n * 128 + row] = dpart[mt * 2 + rp];
            }
    }
    __syncthreads();
    if (d0 == 0 && tid < 128)
        den[h * L + i * 128 + tid] = dn[tid] + dn[128 + tid] + dn[256 + tid] + dn[384 + tid];
}

__global__ void y_kernel(const float* __restrict__ x, const float* __restrict__ qkvh,
                         const float* __restrict__ den, const float* __restrict__ w,
                         const float* __restrict__ b, float* __restrict__ y)
{
    int l = blockIdx.x, tid = threadIdx.x;  // 512 threads
    float t[8];
    float s = 0.f, s2 = 0.f;
#pragma unroll
    for (int r = 0; r < 8; r++) {
        int j = tid + r * 512;
        int h = j & 7, d = j >> 3;
        float v = qkvh[((size_t)(h * L + l)) * D + d] / den[h * L + l];
        t[r] = v; s += v; s2 += v * v;
    }
    float2 red = block_reduce2(s, s2);
    float mu = red.x * (1.0f / DH);
    float rs = rsqrtf(red.y * (1.0f / DH) - mu * mu + 1e-5f);
#pragma unroll
    for (int r = 0; r < 8; r++) {
        int j = tid + r * 512;
        y[(size_t)l * DH + j] = rnd(x[(size_t)l * D + (j >> 3)] + (t[r] - mu) * rs * w[j] + b[j]);
    }
}

__global__ void reduce_h1(const float* __restrict__ part, const float* __restrict__ b1,
                          float* __restrict__ h1)
{
    int q = blockIdx.x * 256 + threadIdx.x;
    const float4* p = (const float4*)part;
    float4 v0 = p[q];
    float4 v1 = p[q + (L * FF / 4)];
    float4 bb = ((const float4*)b1)[q & (FF / 4 - 1)];
    float4 o;
    o.x = rnd(fmaxf(v0.x + v1.x + bb.x, 0.f));
    o.y = rnd(fmaxf(v0.y + v1.y + bb.y, 0.f));
    o.z = rnd(fmaxf(v0.z + v1.z + bb.z, 0.f));
    o.w = rnd(fmaxf(v0.w + v1.w + bb.w, 0.f));
    ((float4*)h1)[q] = o;
}

__global__ void reduce_out(const float* __restrict__ part, const float* __restrict__ b2,
                           const float* __restrict__ x, float* __restrict__ out)
{
    int q = blockIdx.x * 256 + threadIdx.x;
    const float4* p = (const float4*)part;
    float4 v0 = p[q];
    float4 v1 = p[q + 131072];
    float4 v2 = p[q + 262144];
    float4 v3 = p[q + 393216];
    float4 bb = ((const float4*)b2)[q & 127];
    float4 xx = ((const float4*)x)[q];
    float4 o;
    o.x = fmaxf(v0.x + v1.x + v2.x + v3.x + bb.x, 0.f) + xx.x;
    o.y = fmaxf(v0.y + v1.y + v2.y + v3.y + bb.y, 0.f) + xx.y;
    o.z = fmaxf(v0.z + v1.z + v2.z + v3.z + bb.z, 0.f) + xx.z;
    o.w = fmaxf(v0.w + v1.w + v2.w + v3.w + bb.w, 0.f) + xx.w;
    ((float4*)out)[q] = o;
}

extern "C" void kernel_launch(void* const* d_in, const int* in_sizes, int n_in,
                              void* d_out, int out_size)
{
    const float* x    = (const float*)d_in[0];
    const float* ln0w = (const float*)d_in[1];
    const float* ln0b = (const float*)d_in[2];
    const float* ln1w = (const float*)d_in[3];
    const float* ln1b = (const float*)d_in[4];
    const float* qw   = (const float*)d_in[5];
    const float* qb   = (const float*)d_in[6];
    const float* kw   = (const float*)d_in[7];
    const float* kb   = (const float*)d_in[8];
    const float* vw   = (const float*)d_in[9];
    const float* vb   = (const float*)d_in[10];
    const float* w1   = (const float*)d_in[11];
    const float* b1   = (const float*)d_in[12];
    const float* w2   = (const float*)d_in[13];
    const float* b2   = (const float*)d_in[14];
    float* out = (float*)d_out;

    float *xn, *rx, *rqw, *rkw, *rvw, *rw1, *rw2;
    float *qh, *kh, *vh, *den, *qkvh, *y, *h1, *part, *parth, *partq, *partk;
    cudaGetSymbolAddress((void**)&xn,    g_xn);
    cudaGetSymbolAddress((void**)&rx,    g_rx);
    cudaGetSymbolAddress((void**)&rqw,   g_rqw);
    cudaGetSymbolAddress((void**)&rkw,   g_rkw);
    cudaGetSymbolAddress((void**)&rvw,   g_rvw);
    cudaGetSymbolAddress((void**)&rw1,   g_rw1);
    cudaGetSymbolAddress((void**)&rw2,   g_rw2);
    cudaGetSymbolAddress((void**)&qh,    g_qh);
    cudaGetSymbolAddress((void**)&kh,    g_kh);
    cudaGetSymbolAddress((void**)&vh,    g_vh);
    cudaGetSymbolAddress((void**)&den,   g_den);
    cudaGetSymbolAddress((void**)&qkvh,  g_qkvh);
    cudaGetSymbolAddress((void**)&y,     g_y);
    cudaGetSymbolAddress((void**)&h1,    g_h1);
    cudaGetSymbolAddress((void**)&part,  g_part);
    cudaGetSymbolAddress((void**)&parth, g_parth);
    cudaGetSymbolAddress((void**)&partq, g_partq);
    cudaGetSymbolAddress((void**)&partk, g_partk);

    cudaFuncSetAttribute(tgemm<2,1,0,0,1>, cudaFuncAttributeMaxDynamicSharedMemorySize, SMEM_BYTES);
    cudaFuncSetAttribute(tgemm<0,0,0,2,0>, cudaFuncAttributeMaxDynamicSharedMemorySize, SMEM_BYTES);
    cudaFuncSetAttribute(tgemm<0,0,0,3,0>, cudaFuncAttributeMaxDynamicSharedMemorySize, SMEM_BYTES);
    cudaFuncSetAttribute(attn_kernel, cudaFuncAttributeMaxDynamicSharedMemorySize, ATTN_SMEM);

    // 0) round weights + x to tf32
    round_multi<<<12032, 256>>>(qw, kw, vw, w1, w2, x, rqw, rkw, rvw, rw1, rw2, rx);
    // 1) LN0 (rounded)
    ln0_kernel<<<L, 256>>>(x, ln0w, ln0b, xn);
    // 2) q+k projection partials merged (dual splitK=4, z: 0-3 q, 4-7 k)
    tgemm<0,0,0,3,0><<<dim3(AH/TBN, L/TBM, 8), 128, SMEM_BYTES>>>(
        xn, rqw, nullptr, partq, rkw, partk, L, AH, D/4, D);
    // 2b) q,k = rnd(exp(clip(sum+bias))), head-major
    reduce_qk<<<dim3(1024, 2), 256>>>(partq, partk, qb, kb, qh, kh);
    // 3) v projection (+bias, head-major, rounded)
    tgemm<2,1,0,0,1><<<dim3(DH/TBN, L/TBM), 128, SMEM_BYTES>>>(
        rx, rvw, vb, vh, nullptr, nullptr, L, DH, D, D);
    // 4-6) fused: S = tril(QK^T), den = rowsum(S), qkv = S@V
    attn_kernel<<<dim3(8, 8, NH), 256, ATTN_SMEM>>>(qh, kh, vh, qkvh, den);
    // 7) y = x + LN1(qkv/den) (rounded)
    y_kernel<<<L, 512>>>(x, qkvh, den, ln1w, ln1b, y);
    // 8) h1 partials: splitK=2 of y@w1
    tgemm<0,0,0,2,0><<<dim3(FF/TBN, L/TBM, 2), 128, SMEM_BYTES>>>(
        y, rw1, nullptr, parth, nullptr, nullptr, L, FF, DH/2, DH);
    // 8b) h1 = rnd(relu(sum + b1))
    reduce_h1<<<2048, 256>>>(parth, b1, h1);
    // 9) split-K=4 partials of h1@w2
    tgemm<0,0,0,2,0><<<dim3(D/TBN, L/TBM, 4), 128, SMEM_BYTES>>>(
        h1, rw2, nullptr, part, nullptr, nullptr, L, D, FF/4, FF);
    // 10) out = relu(sum+b2)+x
    reduce_out<<<512, 256>>>(part, b2, x, out);
}